// round 11
// baseline (speedup 1.0000x reference)
#include <cuda_runtime.h>
#include <cuda_fp16.h>
#include <cstdint>
#include <math.h>

#define BB 2
#define NN 2048
#define DD 768
#define HH 12
#define HD 64
#define BH (BB*HH)
#define XN (BB*NN*DD)
#define WN (DD*DD)
#define LOG2E 1.4426950408889634f

__device__ __align__(16) __half g_xh[XN], g_xl[XN];
__device__ __align__(16) __half g_wh[3 * WN], g_wl[3 * WN];
__device__ __align__(16) __half g_qh[BH*NN*HD], g_ql[BH*NN*HD];
__device__ __align__(16) __half g_kh[BH*NN*HD], g_kl[BH*NN*HD];
__device__ __align__(16) __half g_vh[BH*NN*HD];

__device__ __forceinline__ uint32_t smem_u32(const void* p) {
    uint32_t a;
    asm("{ .reg .u64 t; cvta.to.shared.u64 t, %1; cvt.u32.u64 %0, t; }" : "=r"(a) : "l"(p));
    return a;
}
__device__ __forceinline__ uint32_t pack2h(float a, float b) {
    __half2 t = __floats2half2_rn(a, b);
    return *reinterpret_cast<uint32_t*>(&t);
}
__device__ __forceinline__ void split2h(float a, float b, uint32_t& hp, uint32_t& lp) {
    __half ha = __float2half_rn(a), hb = __float2half_rn(b);
    __half2 hh = __halves2half2(ha, hb);
    hp = *reinterpret_cast<uint32_t*>(&hh);
    lp = pack2h(a - __half2float(ha), b - __half2float(hb));
}
__device__ __forceinline__ void cpa16(uint32_t dst, const void* src) {
    asm volatile("cp.async.cg.shared.global [%0], [%1], 16;" :: "r"(dst), "l"(src) : "memory");
}
__device__ __forceinline__ void cpa_commit() {
    asm volatile("cp.async.commit_group;" ::: "memory");
}
__device__ __forceinline__ void ldmx4(uint32_t* r, uint32_t addr) {
    asm volatile("ldmatrix.sync.aligned.m8n8.x4.shared.b16 {%0,%1,%2,%3}, [%4];"
        : "=r"(r[0]), "=r"(r[1]), "=r"(r[2]), "=r"(r[3]) : "r"(addr));
}
__device__ __forceinline__ void ldmx4t(uint32_t* r, uint32_t addr) {
    asm volatile("ldmatrix.sync.aligned.m8n8.x4.trans.shared.b16 {%0,%1,%2,%3}, [%4];"
        : "=r"(r[0]), "=r"(r[1]), "=r"(r[2]), "=r"(r[3]) : "r"(addr));
}
__device__ __forceinline__ void mma16816(float* c, const uint32_t* a, uint32_t b0, uint32_t b1) {
    asm volatile("mma.sync.aligned.m16n8k16.row.col.f32.f16.f16.f32 "
        "{%0,%1,%2,%3}, {%4,%5,%6,%7}, {%8,%9}, {%0,%1,%2,%3};"
        : "+f"(c[0]), "+f"(c[1]), "+f"(c[2]), "+f"(c[3])
        : "r"(a[0]), "r"(a[1]), "r"(a[2]), "r"(a[3]), "r"(b0), "r"(b1));
}

// ---------------------------------------------------------------------------
// Split kernel. Wq pre-scaled by log2(e) (softmax invariant to consistent scale).
// ---------------------------------------------------------------------------
__global__ __launch_bounds__(256) void split_kernel(
    const float4* __restrict__ x, const float4* __restrict__ Wq,
    const float4* __restrict__ Wk, const float4* __restrict__ Wv)
{
    const int nx = XN / 4, nw = WN / 4;
    int i = blockIdx.x * 256 + threadIdx.x;
    if (i >= nx + 3 * nw) return;

    float4 v;
    __half *hd, *ld;
    if (i < nx) {
        v = x[i];
        hd = g_xh + (size_t)i * 4; ld = g_xl + (size_t)i * 4;
    } else {
        int j = i - nx;
        int z = j / nw, r = j - z * nw;
        const float4* w = (z == 0) ? Wq : (z == 1) ? Wk : Wv;
        v = w[r];
        if (z == 0) { v.x *= LOG2E; v.y *= LOG2E; v.z *= LOG2E; v.w *= LOG2E; }
        hd = g_wh + (size_t)z * WN + (size_t)r * 4;
        ld = g_wl + (size_t)z * WN + (size_t)r * 4;
    }
    uint32_t h0, l0, h1, l1;
    split2h(v.x, v.y, h0, l0);
    split2h(v.z, v.w, h1, l1);
    *reinterpret_cast<uint2*>(hd) = make_uint2(h0, h1);
    *reinterpret_cast<uint2*>(ld) = make_uint2(l0, l1);
}

// ---------------------------------------------------------------------------
// FUSED QKV projection: one grid, z in {0,1,2}. z<2: fp16 3-term (Q,K, hi/lo
// outputs). z==2: single-term (V). CTA 128x128, 8 warps x (32x64), 2-stage.
// 576 CTAs total -> ~2 full waves at 2 CTAs/SM (fixes wave quantization).
// ---------------------------------------------------------------------------
#define KC 32
#define SROW 40
#define T128_B (128 * SROW * 2)               // 10240
#define QK_STAGE_B (4 * T128_B)               // 40960
#define NCHUNK (DD / KC)                      // 24

__global__ __launch_bounds__(256, 2) void qkv_mma_kernel()
{
    extern __shared__ char smc[];
    const uint32_t sb = smem_u32(smc);

    const int tid = threadIdx.x;
    const int w = tid >> 5, lane = tid & 31;
    const int wm = (w >> 1) * 32;
    const int wn = (w & 1) * 64;
    const int z = blockIdx.z;               // 0=Q, 1=K, 2=V
    const bool three_term = (z < 2);
    const int n0 = blockIdx.x * 128;
    const int m0 = blockIdx.y * 128;

    const __half* __restrict__ Bhp = g_wh + (size_t)z * WN;
    const __half* __restrict__ Blp = g_wl + (size_t)z * WN;

    auto load_chunk = [&](int kt, int stage) {
        const int kb = kt * KC;
        const uint32_t st = sb + stage * QK_STAGE_B;
        #pragma unroll
        for (int i = 0; i < 2; ++i) {
            int id = tid + i * 256;
            int r = id >> 2, c = id & 3;
            uint32_t doff = (uint32_t)(r * 80 + c * 16);
            size_t gA = (size_t)(m0 + r) * DD + kb + c * 8;
            size_t gB = (size_t)(n0 + r) * DD + kb + c * 8;
            cpa16(st + 0 * T128_B + doff, g_xh + gA);
            cpa16(st + 2 * T128_B + doff, Bhp + gB);
            if (three_term) {
                cpa16(st + 1 * T128_B + doff, g_xl + gA);
                cpa16(st + 3 * T128_B + doff, Blp + gB);
            }
        }
        cpa_commit();
    };

    float acc[2][8][4] = {};

    load_chunk(0, 0);
    load_chunk(1, 1);

    const int lrow = lane & 15;
    const int lcol = ((lane >> 4) & 1) * 8;

    for (int kt = 0; kt < NCHUNK; ++kt) {
        if (kt < NCHUNK - 1)
            asm volatile("cp.async.wait_group 1;" ::: "memory");
        else
            asm volatile("cp.async.wait_group 0;" ::: "memory");
        __syncthreads();

        const uint32_t st = sb + (kt & 1) * QK_STAGE_B;

        #pragma unroll
        for (int ks = 0; ks < 2; ++ks) {
            const int kc = ks * 16 + lcol;
            uint32_t bh[4][4], bl[4][4];
            #pragma unroll
            for (int fp = 0; fp < 4; ++fp) {
                uint32_t off = (uint32_t)((wn + fp * 16 + lrow) * SROW + kc) * 2;
                ldmx4(bh[fp], st + 2 * T128_B + off);
                if (three_term) ldmx4(bl[fp], st + 3 * T128_B + off);
            }
            #pragma unroll
            for (int mf = 0; mf < 2; ++mf) {
                uint32_t ah[4], al[4];
                uint32_t off = (uint32_t)((wm + mf * 16 + lrow) * SROW + kc) * 2;
                ldmx4(ah, st + 0 * T128_B + off);
                if (three_term) ldmx4(al, st + 1 * T128_B + off);
                // term 1: Ah*Bh
                #pragma unroll
                for (int fn = 0; fn < 8; ++fn) {
                    const int p = fn >> 1, f = fn & 1;
                    mma16816(acc[mf][fn], ah, bh[p][f], bh[p][f + 2]);
                }
                if (three_term) {
                    // term 2: Ah*Bl
                    #pragma unroll
                    for (int fn = 0; fn < 8; ++fn) {
                        const int p = fn >> 1, f = fn & 1;
                        mma16816(acc[mf][fn], ah, bl[p][f], bl[p][f + 2]);
                    }
                    // term 3: Al*Bh
                    #pragma unroll
                    for (int fn = 0; fn < 8; ++fn) {
                        const int p = fn >> 1, f = fn & 1;
                        mma16816(acc[mf][fn], al, bh[p][f], bh[p][f + 2]);
                    }
                }
            }
        }
        __syncthreads();
        if (kt + 2 < NCHUNK) load_chunk(kt + 2, kt & 1);
    }

    const int trow = lane >> 2;
    const int tcol = (lane & 3) * 2;
    if (three_term) {
        __half* Oh = (z == 0) ? g_qh : g_kh;
        __half* Ol = (z == 0) ? g_ql : g_kl;
        #pragma unroll
        for (int mf = 0; mf < 2; ++mf) {
            #pragma unroll
            for (int fn = 0; fn < 8; ++fn) {
                int o = n0 + wn + fn * 8 + tcol;
                int h = o >> 6, cb = o & 63;
                #pragma unroll
                for (int half = 0; half < 2; ++half) {
                    int row = m0 + wm + mf * 16 + trow + half * 8;
                    int b = row >> 11, n = row & (NN - 1);
                    size_t idx = (((size_t)(b * HH + h)) * NN + n) * HD + cb;
                    uint32_t hp, lp;
                    split2h(acc[mf][fn][half * 2], acc[mf][fn][half * 2 + 1], hp, lp);
                    *reinterpret_cast<uint32_t*>(Oh + idx) = hp;
                    *reinterpret_cast<uint32_t*>(Ol + idx) = lp;
                }
            }
        }
    } else {
        #pragma unroll
        for (int mf = 0; mf < 2; ++mf) {
            #pragma unroll
            for (int fn = 0; fn < 8; ++fn) {
                int o = n0 + wn + fn * 8 + tcol;
                int h = o >> 6, cb = o & 63;
                #pragma unroll
                for (int half = 0; half < 2; ++half) {
                    int row = m0 + wm + mf * 16 + trow + half * 8;
                    int b = row >> 11, n = row & (NN - 1);
                    size_t idx = (((size_t)(b * HH + h)) * NN + n) * HD + cb;
                    *reinterpret_cast<uint32_t*>(g_vh + idx) =
                        pack2h(acc[mf][fn][half * 2], acc[mf][fn][half * 2 + 1]);
                }
            }
        }
    }
}

// ---------------------------------------------------------------------------
// Flash attention: BLOCK_M=64, 4 warps x 16 rows, BLOCK_N=64.
// S 3-term fp16 (terms separated), PV single-term. 3 CTAs/SM. exp2 domain.
// ---------------------------------------------------------------------------
#define VROW 72
#define KVTILE_B (64 * VROW * 2)    // 9216
#define KVSTAGE_B (3 * KVTILE_B)    // 27648

__global__ __launch_bounds__(128, 3) void flash_mma_kernel(float* __restrict__ out)
{
    extern __shared__ char smc[];
    const uint32_t sb = smem_u32(smc);
    const int tid = threadIdx.x, wid = tid >> 5, lane = tid & 31;
    const int bh = blockIdx.y;
    const int qt = (int)gridDim.x - 1 - (int)blockIdx.x;   // heavy tiles first
    const int qbase = qt * 64;
    const int wm = wid * 16;
    const int rowmax = qbase + wm + 15;

    const size_t base = (size_t)bh * NN * HD;
    const __half* __restrict__ Qhp = g_qh + base;
    const __half* __restrict__ Qlp = g_ql + base;
    const __half* __restrict__ Khp = g_kh + base;
    const __half* __restrict__ Klp = g_kl + base;
    const __half* __restrict__ Vhp = g_vh + base;

    // Q fragments (16 rows per warp)
    uint32_t qh[4][4], ql[4][4];
    {
        const int r0 = qbase + wm + (lane >> 2);
        const int c0 = (lane & 3) * 2;
        #pragma unroll
        for (int kk = 0; kk < 4; ++kk) {
            #pragma unroll
            for (int jj = 0; jj < 4; ++jj) {
                int row = r0 + (jj & 1) * 8;
                int col = kk * 16 + c0 + (jj >> 1) * 8;
                qh[kk][jj] = *reinterpret_cast<const uint32_t*>(Qhp + (size_t)row * HD + col);
                ql[kk][jj] = *reinterpret_cast<const uint32_t*>(Qlp + (size_t)row * HD + col);
            }
        }
    }

    auto load_kv = [&](int j, int stage) {
        const int kb = j * 64;
        const uint32_t st = sb + stage * KVSTAGE_B;
        #pragma unroll
        for (int i = 0; i < 4; ++i) {
            int id = tid + i * 128;
            int r = id >> 3, c = id & 7;
            uint32_t doff = (uint32_t)(r * 144 + c * 16);
            size_t go = (size_t)(kb + r) * HD + c * 8;
            cpa16(st + 0 * KVTILE_B + doff, Khp + go);
            cpa16(st + 1 * KVTILE_B + doff, Klp + go);
            cpa16(st + 2 * KVTILE_B + doff, Vhp + go);
        }
        cpa_commit();
    };

    float o[8][4] = {};
    float mi0 = -1e30f, mi1 = -1e30f, li0 = 0.0f, li1 = 0.0f;

    const int ntiles = qt + 1;
    load_kv(0, 0);
    if (ntiles > 1) load_kv(1, 1);

    const int lrow = lane & 15;
    const int lcol = ((lane >> 4) & 1) * 8;
    const int vrow_base = (lane & 7) + ((lane >> 3) & 1) * 8;
    const int vcol = ((lane >> 4) & 1) * 8;

    for (int j = 0; j < ntiles; ++j) {
        if (j < ntiles - 1)
            asm volatile("cp.async.wait_group 1;" ::: "memory");
        else
            asm volatile("cp.async.wait_group 0;" ::: "memory");
        __syncthreads();

        const int j64 = 64 * j;
        const int nlim = rowmax - j64;
        const uint32_t st = sb + (j & 1) * KVSTAGE_B;

        // ---- S = Q K^T (fp16 3-term, terms separated per np block) ----
        float s[8][4] = {};
        #pragma unroll
        for (int kk = 0; kk < 4; ++kk) {
            const int kc = kk * 16 + lcol;
            #pragma unroll
            for (int np = 0; np < 4; ++np) {
                if (np * 16 <= nlim) {
                    uint32_t bkh[4], bkl[4];
                    uint32_t off = (uint32_t)((np * 16 + lrow) * VROW + kc) * 2;
                    ldmx4(bkh, st + 0 * KVTILE_B + off);
                    ldmx4(bkl, st + 1 * KVTILE_B + off);
                    const int fn0 = np * 2;
                    mma16816(s[fn0 + 0], qh[kk], bkh[0], bkh[2]);
                    mma16816(s[fn0 + 1], qh[kk], bkh[1], bkh[3]);
                    mma16816(s[fn0 + 0], qh[kk], bkl[0], bkl[2]);
                    mma16816(s[fn0 + 1], qh[kk], bkl[1], bkl[3]);
                    mma16816(s[fn0 + 0], ql[kk], bkh[0], bkh[2]);
                    mma16816(s[fn0 + 1], ql[kk], bkh[1], bkh[3]);
                }
            }
        }

        // ---- causal mask (last tile only) ----
        if (j == qt) {
            const int rg0 = qbase + wm + (lane >> 2);
            #pragma unroll
            for (int fn = 0; fn < 8; ++fn) {
                const int cb = j64 + fn * 8 + (lane & 3) * 2;
                if (cb + 0 > rg0)     s[fn][0] = -1e30f;
                if (cb + 1 > rg0)     s[fn][1] = -1e30f;
                if (cb + 0 > rg0 + 8) s[fn][2] = -1e30f;
                if (cb + 1 > rg0 + 8) s[fn][3] = -1e30f;
            }
        }

        // ---- online softmax (exp2 domain) ----
        {
            float m0n = mi0, m1n = mi1;
            #pragma unroll
            for (int fn = 0; fn < 8; ++fn) {
                m0n = fmaxf(m0n, fmaxf(s[fn][0], s[fn][1]));
                m1n = fmaxf(m1n, fmaxf(s[fn][2], s[fn][3]));
            }
            m0n = fmaxf(m0n, __shfl_xor_sync(0xffffffffu, m0n, 1));
            m0n = fmaxf(m0n, __shfl_xor_sync(0xffffffffu, m0n, 2));
            m1n = fmaxf(m1n, __shfl_xor_sync(0xffffffffu, m1n, 1));
            m1n = fmaxf(m1n, __shfl_xor_sync(0xffffffffu, m1n, 2));

            const float al0 = exp2f(mi0 - m0n);
            const float al1 = exp2f(mi1 - m1n);
            mi0 = m0n; mi1 = m1n;

            float rs0 = 0.0f, rs1 = 0.0f;
            #pragma unroll
            for (int fn = 0; fn < 8; ++fn) {
                s[fn][0] = exp2f(s[fn][0] - m0n);
                s[fn][1] = exp2f(s[fn][1] - m0n);
                s[fn][2] = exp2f(s[fn][2] - m1n);
                s[fn][3] = exp2f(s[fn][3] - m1n);
                rs0 += s[fn][0] + s[fn][1];
                rs1 += s[fn][2] + s[fn][3];
            }
            rs0 += __shfl_xor_sync(0xffffffffu, rs0, 1);
            rs0 += __shfl_xor_sync(0xffffffffu, rs0, 2);
            rs1 += __shfl_xor_sync(0xffffffffu, rs1, 1);
            rs1 += __shfl_xor_sync(0xffffffffu, rs1, 2);
            li0 = li0 * al0 + rs0;
            li1 = li1 * al1 + rs1;

            #pragma unroll
            for (int fn = 0; fn < 8; ++fn) {
                o[fn][0] *= al0; o[fn][1] *= al0;
                o[fn][2] *= al1; o[fn][3] *= al1;
            }
        }

        // ---- O += P V (single-term fp16), skip masked kk blocks ----
        #pragma unroll
        for (int kk = 0; kk < 4; ++kk) {
            if (kk * 16 <= nlim) {
                uint32_t ph[4];
                ph[0] = pack2h(s[2*kk    ][0], s[2*kk    ][1]);
                ph[1] = pack2h(s[2*kk    ][2], s[2*kk    ][3]);
                ph[2] = pack2h(s[2*kk + 1][0], s[2*kk + 1][1]);
                ph[3] = pack2h(s[2*kk + 1][2], s[2*kk + 1][3]);
                #pragma unroll
                for (int dp = 0; dp < 4; ++dp) {
                    const int vrow = kk * 16 + vrow_base;
                    uint32_t off = (uint32_t)(vrow * VROW + dp * 16 + vcol) * 2;
                    uint32_t vh_[4];
                    ldmx4t(vh_, st + 2 * KVTILE_B + off);
                    mma16816(o[dp*2 + 0], ph, vh_[0], vh_[1]);
                    mma16816(o[dp*2 + 1], ph, vh_[2], vh_[3]);
                }
            }
        }

        __syncthreads();
        if (j + 2 < ntiles) load_kv(j + 2, j & 1);
    }

    // ---- epilogue ----
    const int b = bh / HH, h = bh % HH;
    const float inv0 = 1.0f / li0, inv1 = 1.0f / li1;
    const int r0 = qbase + wm + (lane >> 2);
    const int c0 = (lane & 3) * 2;
    #pragma unroll
    for (int fn = 0; fn < 8; ++fn) {
        const int col = h * HD + fn * 8 + c0;
        float* d0 = out + ((size_t)(b * NN + r0)) * DD + col;
        float* d1 = out + ((size_t)(b * NN + r0 + 8)) * DD + col;
        *reinterpret_cast<float2*>(d0) = make_float2(o[fn][0] * inv0, o[fn][1] * inv0);
        *reinterpret_cast<float2*>(d1) = make_float2(o[fn][2] * inv1, o[fn][3] * inv1);
    }
}

static const int QKV_SMEM   = 2 * QK_STAGE_B;   // 81920
static const int FLASH_SMEM = 2 * KVSTAGE_B;    // 55296

extern "C" void kernel_launch(void* const* d_in, const int* in_sizes, int n_in,
                              void* d_out, int out_size)
{
    const float* x  = (const float*)d_in[0];
    const float* Wq = (const float*)d_in[1];
    const float* Wk = (const float*)d_in[2];
    const float* Wv = (const float*)d_in[3];
    float* out = (float*)d_out;

    cudaFuncSetAttribute(qkv_mma_kernel, cudaFuncAttributeMaxDynamicSharedMemorySize, QKV_SMEM);
    cudaFuncSetAttribute(flash_mma_kernel, cudaFuncAttributeMaxDynamicSharedMemorySize, FLASH_SMEM);

    int total4 = XN / 4 + 3 * (WN / 4);
    split_kernel<<<(total4 + 255) / 256, 256>>>(
        (const float4*)x, (const float4*)Wq, (const float4*)Wk, (const float4*)Wv);

    // fused Q+K+V projections: 6 x 32 x 3 = 576 CTAs -> ~2 full waves
    qkv_mma_kernel<<<dim3(DD / 128, (BB * NN) / 128, 3), 256, QKV_SMEM>>>();

    flash_mma_kernel<<<dim3(NN / 64, BH), 128, FLASH_SMEM>>>(out);
}

// round 12
// speedup vs baseline: 1.5618x; 1.5618x over previous
#include <cuda_runtime.h>
#include <cuda_fp16.h>
#include <cstdint>
#include <math.h>

#define BB 2
#define NN 2048
#define DD 768
#define HH 12
#define HD 64
#define BH (BB*HH)
#define XN (BB*NN*DD)
#define WN (DD*DD)
#define LOG2E 1.4426950408889634f

__device__ __align__(16) __half g_xh[XN], g_xl[XN];
__device__ __align__(16) __half g_wh[3 * WN], g_wl[3 * WN];
__device__ __align__(16) __half g_qh[BH*NN*HD], g_ql[BH*NN*HD];
__device__ __align__(16) __half g_kh[BH*NN*HD], g_kl[BH*NN*HD];
__device__ __align__(16) __half g_vh[BH*NN*HD];

__device__ __forceinline__ uint32_t smem_u32(const void* p) {
    uint32_t a;
    asm("{ .reg .u64 t; cvta.to.shared.u64 t, %1; cvt.u32.u64 %0, t; }" : "=r"(a) : "l"(p));
    return a;
}
__device__ __forceinline__ uint32_t pack2h(float a, float b) {
    __half2 t = __floats2half2_rn(a, b);
    return *reinterpret_cast<uint32_t*>(&t);
}
__device__ __forceinline__ void split2h(float a, float b, uint32_t& hp, uint32_t& lp) {
    __half ha = __float2half_rn(a), hb = __float2half_rn(b);
    __half2 hh = __halves2half2(ha, hb);
    hp = *reinterpret_cast<uint32_t*>(&hh);
    lp = pack2h(a - __half2float(ha), b - __half2float(hb));
}
__device__ __forceinline__ void cpa16(uint32_t dst, const void* src) {
    asm volatile("cp.async.cg.shared.global [%0], [%1], 16;" :: "r"(dst), "l"(src) : "memory");
}
__device__ __forceinline__ void cpa_commit() {
    asm volatile("cp.async.commit_group;" ::: "memory");
}
__device__ __forceinline__ void ldmx4(uint32_t* r, uint32_t addr) {
    asm volatile("ldmatrix.sync.aligned.m8n8.x4.shared.b16 {%0,%1,%2,%3}, [%4];"
        : "=r"(r[0]), "=r"(r[1]), "=r"(r[2]), "=r"(r[3]) : "r"(addr));
}
__device__ __forceinline__ void ldmx4t(uint32_t* r, uint32_t addr) {
    asm volatile("ldmatrix.sync.aligned.m8n8.x4.trans.shared.b16 {%0,%1,%2,%3}, [%4];"
        : "=r"(r[0]), "=r"(r[1]), "=r"(r[2]), "=r"(r[3]) : "r"(addr));
}
__device__ __forceinline__ void mma16816(float* c, const uint32_t* a, uint32_t b0, uint32_t b1) {
    asm volatile("mma.sync.aligned.m16n8k16.row.col.f32.f16.f16.f32 "
        "{%0,%1,%2,%3}, {%4,%5,%6,%7}, {%8,%9}, {%0,%1,%2,%3};"
        : "+f"(c[0]), "+f"(c[1]), "+f"(c[2]), "+f"(c[3])
        : "r"(a[0]), "r"(a[1]), "r"(a[2]), "r"(a[3]), "r"(b0), "r"(b1));
}

// ---------------------------------------------------------------------------
// Split kernel. Wq pre-scaled by log2(e) (softmax invariant to consistent scale).
// ---------------------------------------------------------------------------
__global__ __launch_bounds__(256) void split_kernel(
    const float4* __restrict__ x, const float4* __restrict__ Wq,
    const float4* __restrict__ Wk, const float4* __restrict__ Wv)
{
    const int nx = XN / 4, nw = WN / 4;
    int i = blockIdx.x * 256 + threadIdx.x;
    if (i >= nx + 3 * nw) return;

    float4 v;
    __half *hd, *ld;
    if (i < nx) {
        v = x[i];
        hd = g_xh + (size_t)i * 4; ld = g_xl + (size_t)i * 4;
    } else {
        int j = i - nx;
        int z = j / nw, r = j - z * nw;
        const float4* w = (z == 0) ? Wq : (z == 1) ? Wk : Wv;
        v = w[r];
        if (z == 0) { v.x *= LOG2E; v.y *= LOG2E; v.z *= LOG2E; v.w *= LOG2E; }
        hd = g_wh + (size_t)z * WN + (size_t)r * 4;
        ld = g_wl + (size_t)z * WN + (size_t)r * 4;
    }
    uint32_t h0, l0, h1, l1;
    split2h(v.x, v.y, h0, l0);
    split2h(v.z, v.w, h1, l1);
    *reinterpret_cast<uint2*>(hd) = make_uint2(h0, h1);
    *reinterpret_cast<uint2*>(ld) = make_uint2(l0, l1);
}

// ---------------------------------------------------------------------------
// Q/K projection: CTA 128(M) x 128(N), 8 warps x (32x64), fp16 3-term, 2-stage.
// ---------------------------------------------------------------------------
#define KC 32
#define SROW 40
#define T128_B (128 * SROW * 2)               // 10240
#define QK_STAGE_B (4 * T128_B)               // 40960
#define NCHUNK (DD / KC)                      // 24

__global__ __launch_bounds__(256, 2) void qk_mma_kernel()
{
    extern __shared__ char smc[];
    const uint32_t sb = smem_u32(smc);

    const int tid = threadIdx.x;
    const int w = tid >> 5, lane = tid & 31;
    const int wm = (w >> 1) * 32;
    const int wn = (w & 1) * 64;
    const int z = blockIdx.z;               // 0=Q, 1=K
    const int n0 = blockIdx.x * 128;
    const int m0 = blockIdx.y * 128;

    const __half* __restrict__ Bhp = g_wh + (size_t)z * WN;
    const __half* __restrict__ Blp = g_wl + (size_t)z * WN;

    auto load_chunk = [&](int kt, int stage) {
        const int kb = kt * KC;
        const uint32_t st = sb + stage * QK_STAGE_B;
        #pragma unroll
        for (int i = 0; i < 2; ++i) {
            int id = tid + i * 256;
            int r = id >> 2, c = id & 3;
            uint32_t doff = (uint32_t)(r * 80 + c * 16);
            size_t gA = (size_t)(m0 + r) * DD + kb + c * 8;
            size_t gB = (size_t)(n0 + r) * DD + kb + c * 8;
            cpa16(st + 0 * T128_B + doff, g_xh + gA);
            cpa16(st + 1 * T128_B + doff, g_xl + gA);
            cpa16(st + 2 * T128_B + doff, Bhp + gB);
            cpa16(st + 3 * T128_B + doff, Blp + gB);
        }
        cpa_commit();
    };

    float acc[2][8][4] = {};

    load_chunk(0, 0);
    load_chunk(1, 1);

    const int lrow = lane & 15;
    const int lcol = ((lane >> 4) & 1) * 8;

    for (int kt = 0; kt < NCHUNK; ++kt) {
        if (kt < NCHUNK - 1)
            asm volatile("cp.async.wait_group 1;" ::: "memory");
        else
            asm volatile("cp.async.wait_group 0;" ::: "memory");
        __syncthreads();

        const uint32_t st = sb + (kt & 1) * QK_STAGE_B;

        #pragma unroll
        for (int ks = 0; ks < 2; ++ks) {
            const int kc = ks * 16 + lcol;
            uint32_t bh[4][4], bl[4][4];
            #pragma unroll
            for (int fp = 0; fp < 4; ++fp) {
                uint32_t off = (uint32_t)((wn + fp * 16 + lrow) * SROW + kc) * 2;
                ldmx4(bh[fp], st + 2 * T128_B + off);
                ldmx4(bl[fp], st + 3 * T128_B + off);
            }
            #pragma unroll
            for (int mf = 0; mf < 2; ++mf) {
                uint32_t ah[4], al[4];
                uint32_t off = (uint32_t)((wm + mf * 16 + lrow) * SROW + kc) * 2;
                ldmx4(ah, st + 0 * T128_B + off);
                ldmx4(al, st + 1 * T128_B + off);
                #pragma unroll
                for (int fn = 0; fn < 8; ++fn) {
                    const int p = fn >> 1, f = fn & 1;
                    mma16816(acc[mf][fn], ah, bh[p][f], bh[p][f + 2]);
                }
                #pragma unroll
                for (int fn = 0; fn < 8; ++fn) {
                    const int p = fn >> 1, f = fn & 1;
                    mma16816(acc[mf][fn], ah, bl[p][f], bl[p][f + 2]);
                }
                #pragma unroll
                for (int fn = 0; fn < 8; ++fn) {
                    const int p = fn >> 1, f = fn & 1;
                    mma16816(acc[mf][fn], al, bh[p][f], bh[p][f + 2]);
                }
            }
        }
        __syncthreads();
        if (kt + 2 < NCHUNK) load_chunk(kt + 2, kt & 1);
    }

    __half* Oh = (z == 0) ? g_qh : g_kh;
    __half* Ol = (z == 0) ? g_ql : g_kl;
    const int trow = lane >> 2;
    const int tcol = (lane & 3) * 2;
    #pragma unroll
    for (int mf = 0; mf < 2; ++mf) {
        #pragma unroll
        for (int fn = 0; fn < 8; ++fn) {
            int o = n0 + wn + fn * 8 + tcol;
            int h = o >> 6, cb = o & 63;
            #pragma unroll
            for (int half = 0; half < 2; ++half) {
                int row = m0 + wm + mf * 16 + trow + half * 8;
                int b = row >> 11, n = row & (NN - 1);
                size_t idx = (((size_t)(b * HH + h)) * NN + n) * HD + cb;
                uint32_t hp, lp;
                split2h(acc[mf][fn][half * 2], acc[mf][fn][half * 2 + 1], hp, lp);
                *reinterpret_cast<uint32_t*>(Oh + idx) = hp;
                *reinterpret_cast<uint32_t*>(Ol + idx) = lp;
            }
        }
    }
}

// ---------------------------------------------------------------------------
// V projection: single-term fp16, CTA 128x128, 8 warps x (32x64).
// ---------------------------------------------------------------------------
#define V_STAGE_B (2 * T128_B)    // 20480

__global__ __launch_bounds__(256, 2) void v_mma_kernel()
{
    extern __shared__ char smc[];
    const uint32_t sb = smem_u32(smc);

    const int tid = threadIdx.x;
    const int w = tid >> 5, lane = tid & 31;
    const int wm = (w >> 1) * 32;
    const int wn = (w & 1) * 64;
    const int n0 = blockIdx.x * 128;
    const int m0 = blockIdx.y * 128;

    const __half* __restrict__ Bhp = g_wh + (size_t)2 * WN;

    auto load_chunk = [&](int kt, int stage) {
        const int kb = kt * KC;
        const uint32_t st = sb + stage * V_STAGE_B;
        #pragma unroll
        for (int i = 0; i < 2; ++i) {
            int id = tid + i * 256;
            int r = id >> 2, c = id & 3;
            uint32_t doff = (uint32_t)(r * 80 + c * 16);
            cpa16(st + doff, g_xh + (size_t)(m0 + r) * DD + kb + c * 8);
            cpa16(st + T128_B + doff, Bhp + (size_t)(n0 + r) * DD + kb + c * 8);
        }
        cpa_commit();
    };

    float acc[2][8][4] = {};

    load_chunk(0, 0);
    load_chunk(1, 1);

    const int lrow = lane & 15;
    const int lcol = ((lane >> 4) & 1) * 8;

    for (int kt = 0; kt < NCHUNK; ++kt) {
        if (kt < NCHUNK - 1)
            asm volatile("cp.async.wait_group 1;" ::: "memory");
        else
            asm volatile("cp.async.wait_group 0;" ::: "memory");
        __syncthreads();

        const uint32_t st = sb + (kt & 1) * V_STAGE_B;

        #pragma unroll
        for (int ks = 0; ks < 2; ++ks) {
            const int kc = ks * 16 + lcol;
            uint32_t bh[4][4];
            #pragma unroll
            for (int fp = 0; fp < 4; ++fp) {
                uint32_t off = (uint32_t)((wn + fp * 16 + lrow) * SROW + kc) * 2;
                ldmx4(bh[fp], st + T128_B + off);
            }
            #pragma unroll
            for (int mf = 0; mf < 2; ++mf) {
                uint32_t ah[4];
                uint32_t off = (uint32_t)((wm + mf * 16 + lrow) * SROW + kc) * 2;
                ldmx4(ah, st + off);
                #pragma unroll
                for (int fn = 0; fn < 8; ++fn) {
                    const int p = fn >> 1, f = fn & 1;
                    mma16816(acc[mf][fn], ah, bh[p][f], bh[p][f + 2]);
                }
            }
        }
        __syncthreads();
        if (kt + 2 < NCHUNK) load_chunk(kt + 2, kt & 1);
    }

    const int trow = lane >> 2;
    const int tcol = (lane & 3) * 2;
    #pragma unroll
    for (int mf = 0; mf < 2; ++mf) {
        #pragma unroll
        for (int fn = 0; fn < 8; ++fn) {
            int o = n0 + wn + fn * 8 + tcol;
            int h = o >> 6, cb = o & 63;
            #pragma unroll
            for (int half = 0; half < 2; ++half) {
                int row = m0 + wm + mf * 16 + trow + half * 8;
                int b = row >> 11, n = row & (NN - 1);
                size_t idx = (((size_t)(b * HH + h)) * NN + n) * HD + cb;
                *reinterpret_cast<uint32_t*>(g_vh + idx) =
                    pack2h(acc[mf][fn][half * 2], acc[mf][fn][half * 2 + 1]);
            }
        }
    }
}

// ---------------------------------------------------------------------------
// Flash attention: BLOCK_M=64, 4 warps x 16 rows, BLOCK_N=64.
// S 3-term fp16 (terms separated), PV single-term. 3 CTAs/SM. exp2 domain.
// ---------------------------------------------------------------------------
#define VROW 72
#define KVTILE_B (64 * VROW * 2)    // 9216
#define KVSTAGE_B (3 * KVTILE_B)    // 27648

__global__ __launch_bounds__(128, 3) void flash_mma_kernel(float* __restrict__ out)
{
    extern __shared__ char smc[];
    const uint32_t sb = smem_u32(smc);
    const int tid = threadIdx.x, wid = tid >> 5, lane = tid & 31;
    const int bh = blockIdx.y;
    const int qt = (int)gridDim.x - 1 - (int)blockIdx.x;   // heavy tiles first
    const int qbase = qt * 64;
    const int wm = wid * 16;
    const int rowmax = qbase + wm + 15;

    const size_t base = (size_t)bh * NN * HD;
    const __half* __restrict__ Qhp = g_qh + base;
    const __half* __restrict__ Qlp = g_ql + base;
    const __half* __restrict__ Khp = g_kh + base;
    const __half* __restrict__ Klp = g_kl + base;
    const __half* __restrict__ Vhp = g_vh + base;

    uint32_t qh[4][4], ql[4][4];
    {
        const int r0 = qbase + wm + (lane >> 2);
        const int c0 = (lane & 3) * 2;
        #pragma unroll
        for (int kk = 0; kk < 4; ++kk) {
            #pragma unroll
            for (int jj = 0; jj < 4; ++jj) {
                int row = r0 + (jj & 1) * 8;
                int col = kk * 16 + c0 + (jj >> 1) * 8;
                qh[kk][jj] = *reinterpret_cast<const uint32_t*>(Qhp + (size_t)row * HD + col);
                ql[kk][jj] = *reinterpret_cast<const uint32_t*>(Qlp + (size_t)row * HD + col);
            }
        }
    }

    auto load_kv = [&](int j, int stage) {
        const int kb = j * 64;
        const uint32_t st = sb + stage * KVSTAGE_B;
        #pragma unroll
        for (int i = 0; i < 4; ++i) {
            int id = tid + i * 128;
            int r = id >> 3, c = id & 7;
            uint32_t doff = (uint32_t)(r * 144 + c * 16);
            size_t go = (size_t)(kb + r) * HD + c * 8;
            cpa16(st + 0 * KVTILE_B + doff, Khp + go);
            cpa16(st + 1 * KVTILE_B + doff, Klp + go);
            cpa16(st + 2 * KVTILE_B + doff, Vhp + go);
        }
        cpa_commit();
    };

    float o[8][4] = {};
    float mi0 = -1e30f, mi1 = -1e30f, li0 = 0.0f, li1 = 0.0f;

    const int ntiles = qt + 1;
    load_kv(0, 0);
    if (ntiles > 1) load_kv(1, 1);

    const int lrow = lane & 15;
    const int lcol = ((lane >> 4) & 1) * 8;
    const int vrow_base = (lane & 7) + ((lane >> 3) & 1) * 8;
    const int vcol = ((lane >> 4) & 1) * 8;

    for (int j = 0; j < ntiles; ++j) {
        if (j < ntiles - 1)
            asm volatile("cp.async.wait_group 1;" ::: "memory");
        else
            asm volatile("cp.async.wait_group 0;" ::: "memory");
        __syncthreads();

        const int j64 = 64 * j;
        const int nlim = rowmax - j64;
        const uint32_t st = sb + (j & 1) * KVSTAGE_B;

        // ---- S = Q K^T (fp16 3-term, terms separated per np block) ----
        float s[8][4] = {};
        #pragma unroll
        for (int kk = 0; kk < 4; ++kk) {
            const int kc = kk * 16 + lcol;
            #pragma unroll
            for (int np = 0; np < 4; ++np) {
                if (np * 16 <= nlim) {
                    uint32_t bkh[4], bkl[4];
                    uint32_t off = (uint32_t)((np * 16 + lrow) * VROW + kc) * 2;
                    ldmx4(bkh, st + 0 * KVTILE_B + off);
                    ldmx4(bkl, st + 1 * KVTILE_B + off);
                    const int fn0 = np * 2;
                    mma16816(s[fn0 + 0], qh[kk], bkh[0], bkh[2]);
                    mma16816(s[fn0 + 1], qh[kk], bkh[1], bkh[3]);
                    mma16816(s[fn0 + 0], qh[kk], bkl[0], bkl[2]);
                    mma16816(s[fn0 + 1], qh[kk], bkl[1], bkl[3]);
                    mma16816(s[fn0 + 0], ql[kk], bkh[0], bkh[2]);
                    mma16816(s[fn0 + 1], ql[kk], bkh[1], bkh[3]);
                }
            }
        }

        if (j == qt) {
            const int rg0 = qbase + wm + (lane >> 2);
            #pragma unroll
            for (int fn = 0; fn < 8; ++fn) {
                const int cb = j64 + fn * 8 + (lane & 3) * 2;
                if (cb + 0 > rg0)     s[fn][0] = -1e30f;
                if (cb + 1 > rg0)     s[fn][1] = -1e30f;
                if (cb + 0 > rg0 + 8) s[fn][2] = -1e30f;
                if (cb + 1 > rg0 + 8) s[fn][3] = -1e30f;
            }
        }

        {
            float m0n = mi0, m1n = mi1;
            #pragma unroll
            for (int fn = 0; fn < 8; ++fn) {
                m0n = fmaxf(m0n, fmaxf(s[fn][0], s[fn][1]));
                m1n = fmaxf(m1n, fmaxf(s[fn][2], s[fn][3]));
            }
            m0n = fmaxf(m0n, __shfl_xor_sync(0xffffffffu, m0n, 1));
            m0n = fmaxf(m0n, __shfl_xor_sync(0xffffffffu, m0n, 2));
            m1n = fmaxf(m1n, __shfl_xor_sync(0xffffffffu, m1n, 1));
            m1n = fmaxf(m1n, __shfl_xor_sync(0xffffffffu, m1n, 2));

            const float al0 = exp2f(mi0 - m0n);
            const float al1 = exp2f(mi1 - m1n);
            mi0 = m0n; mi1 = m1n;

            float rs0 = 0.0f, rs1 = 0.0f;
            #pragma unroll
            for (int fn = 0; fn < 8; ++fn) {
                s[fn][0] = exp2f(s[fn][0] - m0n);
                s[fn][1] = exp2f(s[fn][1] - m0n);
                s[fn][2] = exp2f(s[fn][2] - m1n);
                s[fn][3] = exp2f(s[fn][3] - m1n);
                rs0 += s[fn][0] + s[fn][1];
                rs1 += s[fn][2] + s[fn][3];
            }
            rs0 += __shfl_xor_sync(0xffffffffu, rs0, 1);
            rs0 += __shfl_xor_sync(0xffffffffu, rs0, 2);
            rs1 += __shfl_xor_sync(0xffffffffu, rs1, 1);
            rs1 += __shfl_xor_sync(0xffffffffu, rs1, 2);
            li0 = li0 * al0 + rs0;
            li1 = li1 * al1 + rs1;

            #pragma unroll
            for (int fn = 0; fn < 8; ++fn) {
                o[fn][0] *= al0; o[fn][1] *= al0;
                o[fn][2] *= al1; o[fn][3] *= al1;
            }
        }

        #pragma unroll
        for (int kk = 0; kk < 4; ++kk) {
            if (kk * 16 <= nlim) {
                uint32_t ph[4];
                ph[0] = pack2h(s[2*kk    ][0], s[2*kk    ][1]);
                ph[1] = pack2h(s[2*kk    ][2], s[2*kk    ][3]);
                ph[2] = pack2h(s[2*kk + 1][0], s[2*kk + 1][1]);
                ph[3] = pack2h(s[2*kk + 1][2], s[2*kk + 1][3]);
                #pragma unroll
                for (int dp = 0; dp < 4; ++dp) {
                    const int vrow = kk * 16 + vrow_base;
                    uint32_t off = (uint32_t)(vrow * VROW + dp * 16 + vcol) * 2;
                    uint32_t vh_[4];
                    ldmx4t(vh_, st + 2 * KVTILE_B + off);
                    mma16816(o[dp*2 + 0], ph, vh_[0], vh_[1]);
                    mma16816(o[dp*2 + 1], ph, vh_[2], vh_[3]);
                }
            }
        }

        __syncthreads();
        if (j + 2 < ntiles) load_kv(j + 2, j & 1);
    }

    const int b = bh / HH, h = bh % HH;
    const float inv0 = 1.0f / li0, inv1 = 1.0f / li1;
    const int r0 = qbase + wm + (lane >> 2);
    const int c0 = (lane & 3) * 2;
    #pragma unroll
    for (int fn = 0; fn < 8; ++fn) {
        const int col = h * HD + fn * 8 + c0;
        float* d0 = out + ((size_t)(b * NN + r0)) * DD + col;
        float* d1 = out + ((size_t)(b * NN + r0 + 8)) * DD + col;
        *reinterpret_cast<float2*>(d0) = make_float2(o[fn][0] * inv0, o[fn][1] * inv0);
        *reinterpret_cast<float2*>(d1) = make_float2(o[fn][2] * inv1, o[fn][3] * inv1);
    }
}

static const int QK_SMEM    = 2 * QK_STAGE_B;   // 81920
static const int V_SMEM     = 2 * V_STAGE_B;    // 40960
static const int FLASH_SMEM = 2 * KVSTAGE_B;    // 55296

extern "C" void kernel_launch(void* const* d_in, const int* in_sizes, int n_in,
                              void* d_out, int out_size)
{
    const float* x  = (const float*)d_in[0];
    const float* Wq = (const float*)d_in[1];
    const float* Wk = (const float*)d_in[2];
    const float* Wv = (const float*)d_in[3];
    float* out = (float*)d_out;

    // one-time resources (created on the first, non-captured call)
    static cudaStream_t s_v = nullptr;
    static cudaEvent_t e_fork = nullptr, e_join = nullptr;
    if (s_v == nullptr) {
        cudaStreamCreateWithFlags(&s_v, cudaStreamNonBlocking);
        cudaEventCreateWithFlags(&e_fork, cudaEventDisableTiming);
        cudaEventCreateWithFlags(&e_join, cudaEventDisableTiming);
        cudaFuncSetAttribute(qk_mma_kernel, cudaFuncAttributeMaxDynamicSharedMemorySize, QK_SMEM);
        cudaFuncSetAttribute(v_mma_kernel, cudaFuncAttributeMaxDynamicSharedMemorySize, V_SMEM);
        cudaFuncSetAttribute(flash_mma_kernel, cudaFuncAttributeMaxDynamicSharedMemorySize, FLASH_SMEM);
    }

    int total4 = XN / 4 + 3 * (WN / 4);
    split_kernel<<<(total4 + 255) / 256, 256>>>(
        (const float4*)x, (const float4*)Wq, (const float4*)Wk, (const float4*)Wv);

    // fork: v projection runs concurrently with qk (fills qk's partial 2nd wave)
    cudaEventRecord(e_fork, 0);
    cudaStreamWaitEvent(s_v, e_fork, 0);

    qk_mma_kernel<<<dim3(DD / 128, (BB * NN) / 128, 2), 256, QK_SMEM>>>();
    v_mma_kernel<<<dim3(DD / 128, (BB * NN) / 128), 256, V_SMEM, s_v>>>();

    // join
    cudaEventRecord(e_join, s_v);
    cudaStreamWaitEvent(0, e_join, 0);

    flash_mma_kernel<<<dim3(NN / 64, BH), 128, FLASH_SMEM>>>(out);
}

// round 13
// speedup vs baseline: 1.6500x; 1.0565x over previous
#include <cuda_runtime.h>
#include <cuda_fp16.h>
#include <cstdint>
#include <math.h>

#define BB 2
#define NN 2048
#define DD 768
#define HH 12
#define HD 64
#define BH (BB*HH)
#define XN (BB*NN*DD)
#define WN (DD*DD)
#define LOG2E 1.4426950408889634f

__device__ __align__(16) __half g_xh[XN], g_xl[XN];
__device__ __align__(16) __half g_wh[3 * WN], g_wl[3 * WN];
__device__ __align__(16) __half g_qh[BH*NN*HD], g_ql[BH*NN*HD];
__device__ __align__(16) __half g_kh[BH*NN*HD], g_kl[BH*NN*HD];
__device__ __align__(16) __half g_vh[BH*NN*HD];

__device__ __forceinline__ uint32_t smem_u32(const void* p) {
    uint32_t a;
    asm("{ .reg .u64 t; cvta.to.shared.u64 t, %1; cvt.u32.u64 %0, t; }" : "=r"(a) : "l"(p));
    return a;
}
__device__ __forceinline__ uint32_t pack2h(float a, float b) {
    __half2 t = __floats2half2_rn(a, b);
    return *reinterpret_cast<uint32_t*>(&t);
}
__device__ __forceinline__ void split2h(float a, float b, uint32_t& hp, uint32_t& lp) {
    __half ha = __float2half_rn(a), hb = __float2half_rn(b);
    __half2 hh = __halves2half2(ha, hb);
    hp = *reinterpret_cast<uint32_t*>(&hh);
    lp = pack2h(a - __half2float(ha), b - __half2float(hb));
}
__device__ __forceinline__ void cpa16(uint32_t dst, const void* src) {
    asm volatile("cp.async.cg.shared.global [%0], [%1], 16;" :: "r"(dst), "l"(src) : "memory");
}
__device__ __forceinline__ void cpa_commit() {
    asm volatile("cp.async.commit_group;" ::: "memory");
}
__device__ __forceinline__ void ldmx4(uint32_t* r, uint32_t addr) {
    asm volatile("ldmatrix.sync.aligned.m8n8.x4.shared.b16 {%0,%1,%2,%3}, [%4];"
        : "=r"(r[0]), "=r"(r[1]), "=r"(r[2]), "=r"(r[3]) : "r"(addr));
}
__device__ __forceinline__ void ldmx4t(uint32_t* r, uint32_t addr) {
    asm volatile("ldmatrix.sync.aligned.m8n8.x4.trans.shared.b16 {%0,%1,%2,%3}, [%4];"
        : "=r"(r[0]), "=r"(r[1]), "=r"(r[2]), "=r"(r[3]) : "r"(addr));
}
__device__ __forceinline__ void mma16816(float* c, const uint32_t* a, uint32_t b0, uint32_t b1) {
    asm volatile("mma.sync.aligned.m16n8k16.row.col.f32.f16.f16.f32 "
        "{%0,%1,%2,%3}, {%4,%5,%6,%7}, {%8,%9}, {%0,%1,%2,%3};"
        : "+f"(c[0]), "+f"(c[1]), "+f"(c[2]), "+f"(c[3])
        : "r"(a[0]), "r"(a[1]), "r"(a[2]), "r"(a[3]), "r"(b0), "r"(b1));
}

// ---------------------------------------------------------------------------
// Split kernel. Wq pre-scaled by log2(e).
// ---------------------------------------------------------------------------
__global__ __launch_bounds__(256) void split_kernel(
    const float4* __restrict__ x, const float4* __restrict__ Wq,
    const float4* __restrict__ Wk, const float4* __restrict__ Wv)
{
    const int nx = XN / 4, nw = WN / 4;
    int i = blockIdx.x * 256 + threadIdx.x;
    if (i >= nx + 3 * nw) return;

    float4 v;
    __half *hd, *ld;
    if (i < nx) {
        v = x[i];
        hd = g_xh + (size_t)i * 4; ld = g_xl + (size_t)i * 4;
    } else {
        int j = i - nx;
        int z = j / nw, r = j - z * nw;
        const float4* w = (z == 0) ? Wq : (z == 1) ? Wk : Wv;
        v = w[r];
        if (z == 0) { v.x *= LOG2E; v.y *= LOG2E; v.z *= LOG2E; v.w *= LOG2E; }
        hd = g_wh + (size_t)z * WN + (size_t)r * 4;
        ld = g_wl + (size_t)z * WN + (size_t)r * 4;
    }
    uint32_t h0, l0, h1, l1;
    split2h(v.x, v.y, h0, l0);
    split2h(v.z, v.w, h1, l1);
    *reinterpret_cast<uint2*>(hd) = make_uint2(h0, h1);
    *reinterpret_cast<uint2*>(ld) = make_uint2(l0, l1);
}

// ---------------------------------------------------------------------------
// Q/K projection (unchanged from R12 best).
// ---------------------------------------------------------------------------
#define KC 32
#define SROW 40
#define T128_B (128 * SROW * 2)
#define QK_STAGE_B (4 * T128_B)
#define NCHUNK (DD / KC)

__global__ __launch_bounds__(256, 2) void qk_mma_kernel()
{
    extern __shared__ char smc[];
    const uint32_t sb = smem_u32(smc);

    const int tid = threadIdx.x;
    const int w = tid >> 5, lane = tid & 31;
    const int wm = (w >> 1) * 32;
    const int wn = (w & 1) * 64;
    const int z = blockIdx.z;
    const int n0 = blockIdx.x * 128;
    const int m0 = blockIdx.y * 128;

    const __half* __restrict__ Bhp = g_wh + (size_t)z * WN;
    const __half* __restrict__ Blp = g_wl + (size_t)z * WN;

    auto load_chunk = [&](int kt, int stage) {
        const int kb = kt * KC;
        const uint32_t st = sb + stage * QK_STAGE_B;
        #pragma unroll
        for (int i = 0; i < 2; ++i) {
            int id = tid + i * 256;
            int r = id >> 2, c = id & 3;
            uint32_t doff = (uint32_t)(r * 80 + c * 16);
            size_t gA = (size_t)(m0 + r) * DD + kb + c * 8;
            size_t gB = (size_t)(n0 + r) * DD + kb + c * 8;
            cpa16(st + 0 * T128_B + doff, g_xh + gA);
            cpa16(st + 1 * T128_B + doff, g_xl + gA);
            cpa16(st + 2 * T128_B + doff, Bhp + gB);
            cpa16(st + 3 * T128_B + doff, Blp + gB);
        }
        cpa_commit();
    };

    float acc[2][8][4] = {};

    load_chunk(0, 0);
    load_chunk(1, 1);

    const int lrow = lane & 15;
    const int lcol = ((lane >> 4) & 1) * 8;

    for (int kt = 0; kt < NCHUNK; ++kt) {
        if (kt < NCHUNK - 1)
            asm volatile("cp.async.wait_group 1;" ::: "memory");
        else
            asm volatile("cp.async.wait_group 0;" ::: "memory");
        __syncthreads();

        const uint32_t st = sb + (kt & 1) * QK_STAGE_B;

        #pragma unroll
        for (int ks = 0; ks < 2; ++ks) {
            const int kc = ks * 16 + lcol;
            uint32_t bh[4][4], bl[4][4];
            #pragma unroll
            for (int fp = 0; fp < 4; ++fp) {
                uint32_t off = (uint32_t)((wn + fp * 16 + lrow) * SROW + kc) * 2;
                ldmx4(bh[fp], st + 2 * T128_B + off);
                ldmx4(bl[fp], st + 3 * T128_B + off);
            }
            #pragma unroll
            for (int mf = 0; mf < 2; ++mf) {
                uint32_t ah[4], al[4];
                uint32_t off = (uint32_t)((wm + mf * 16 + lrow) * SROW + kc) * 2;
                ldmx4(ah, st + 0 * T128_B + off);
                ldmx4(al, st + 1 * T128_B + off);
                #pragma unroll
                for (int fn = 0; fn < 8; ++fn) {
                    const int p = fn >> 1, f = fn & 1;
                    mma16816(acc[mf][fn], ah, bh[p][f], bh[p][f + 2]);
                }
                #pragma unroll
                for (int fn = 0; fn < 8; ++fn) {
                    const int p = fn >> 1, f = fn & 1;
                    mma16816(acc[mf][fn], ah, bl[p][f], bl[p][f + 2]);
                }
                #pragma unroll
                for (int fn = 0; fn < 8; ++fn) {
                    const int p = fn >> 1, f = fn & 1;
                    mma16816(acc[mf][fn], al, bh[p][f], bh[p][f + 2]);
                }
            }
        }
        __syncthreads();
        if (kt + 2 < NCHUNK) load_chunk(kt + 2, kt & 1);
    }

    __half* Oh = (z == 0) ? g_qh : g_kh;
    __half* Ol = (z == 0) ? g_ql : g_kl;
    const int trow = lane >> 2;
    const int tcol = (lane & 3) * 2;
    #pragma unroll
    for (int mf = 0; mf < 2; ++mf) {
        #pragma unroll
        for (int fn = 0; fn < 8; ++fn) {
            int o = n0 + wn + fn * 8 + tcol;
            int h = o >> 6, cb = o & 63;
            #pragma unroll
            for (int half = 0; half < 2; ++half) {
                int row = m0 + wm + mf * 16 + trow + half * 8;
                int b = row >> 11, n = row & (NN - 1);
                size_t idx = (((size_t)(b * HH + h)) * NN + n) * HD + cb;
                uint32_t hp, lp;
                split2h(acc[mf][fn][half * 2], acc[mf][fn][half * 2 + 1], hp, lp);
                *reinterpret_cast<uint32_t*>(Oh + idx) = hp;
                *reinterpret_cast<uint32_t*>(Ol + idx) = lp;
            }
        }
    }
}

// ---------------------------------------------------------------------------
// V projection (unchanged from R12 best).
// ---------------------------------------------------------------------------
#define V_STAGE_B (2 * T128_B)

__global__ __launch_bounds__(256, 2) void v_mma_kernel()
{
    extern __shared__ char smc[];
    const uint32_t sb = smem_u32(smc);

    const int tid = threadIdx.x;
    const int w = tid >> 5, lane = tid & 31;
    const int wm = (w >> 1) * 32;
    const int wn = (w & 1) * 64;
    const int n0 = blockIdx.x * 128;
    const int m0 = blockIdx.y * 128;

    const __half* __restrict__ Bhp = g_wh + (size_t)2 * WN;

    auto load_chunk = [&](int kt, int stage) {
        const int kb = kt * KC;
        const uint32_t st = sb + stage * V_STAGE_B;
        #pragma unroll
        for (int i = 0; i < 2; ++i) {
            int id = tid + i * 256;
            int r = id >> 2, c = id & 3;
            uint32_t doff = (uint32_t)(r * 80 + c * 16);
            cpa16(st + doff, g_xh + (size_t)(m0 + r) * DD + kb + c * 8);
            cpa16(st + T128_B + doff, Bhp + (size_t)(n0 + r) * DD + kb + c * 8);
        }
        cpa_commit();
    };

    float acc[2][8][4] = {};

    load_chunk(0, 0);
    load_chunk(1, 1);

    const int lrow = lane & 15;
    const int lcol = ((lane >> 4) & 1) * 8;

    for (int kt = 0; kt < NCHUNK; ++kt) {
        if (kt < NCHUNK - 1)
            asm volatile("cp.async.wait_group 1;" ::: "memory");
        else
            asm volatile("cp.async.wait_group 0;" ::: "memory");
        __syncthreads();

        const uint32_t st = sb + (kt & 1) * V_STAGE_B;

        #pragma unroll
        for (int ks = 0; ks < 2; ++ks) {
            const int kc = ks * 16 + lcol;
            uint32_t bh[4][4];
            #pragma unroll
            for (int fp = 0; fp < 4; ++fp) {
                uint32_t off = (uint32_t)((wn + fp * 16 + lrow) * SROW + kc) * 2;
                ldmx4(bh[fp], st + T128_B + off);
            }
            #pragma unroll
            for (int mf = 0; mf < 2; ++mf) {
                uint32_t ah[4];
                uint32_t off = (uint32_t)((wm + mf * 16 + lrow) * SROW + kc) * 2;
                ldmx4(ah, st + off);
                #pragma unroll
                for (int fn = 0; fn < 8; ++fn) {
                    const int p = fn >> 1, f = fn & 1;
                    mma16816(acc[mf][fn], ah, bh[p][f], bh[p][f + 2]);
                }
            }
        }
        __syncthreads();
        if (kt + 2 < NCHUNK) load_chunk(kt + 2, kt & 1);
    }

    const int trow = lane >> 2;
    const int tcol = (lane & 3) * 2;
    #pragma unroll
    for (int mf = 0; mf < 2; ++mf) {
        #pragma unroll
        for (int fn = 0; fn < 8; ++fn) {
            int o = n0 + wn + fn * 8 + tcol;
            int h = o >> 6, cb = o & 63;
            #pragma unroll
            for (int half = 0; half < 2; ++half) {
                int row = m0 + wm + mf * 16 + trow + half * 8;
                int b = row >> 11, n = row & (NN - 1);
                size_t idx = (((size_t)(b * HH + h)) * NN + n) * HD + cb;
                *reinterpret_cast<uint32_t*>(g_vh + idx) =
                    pack2h(acc[mf][fn][half * 2], acc[mf][fn][half * 2 + 1]);
            }
        }
    }
}

// ---------------------------------------------------------------------------
// Flash attention: BLOCK_M=64, 4 warps x 16 rows, BLOCK_N=64, 3 CTAs/SM.
// Dense-tile fast path (no masks): batched ldsm + wide-distance MMA ordering.
// Softmax: packed-fp16 max shuffles, per-lane li partials (no li shuffles),
// conditional rescale. exp2 domain.
// ---------------------------------------------------------------------------
#define VROW 72
#define KVTILE_B (64 * VROW * 2)
#define KVSTAGE_B (3 * KVTILE_B)

__global__ __launch_bounds__(128, 3) void flash_mma_kernel(float* __restrict__ out)
{
    extern __shared__ char smc[];
    const uint32_t sb = smem_u32(smc);
    const int tid = threadIdx.x, wid = tid >> 5, lane = tid & 31;
    const int bh = blockIdx.y;
    const int qt = (int)gridDim.x - 1 - (int)blockIdx.x;   // heavy tiles first
    const int qbase = qt * 64;
    const int wm = wid * 16;
    const int rowmax = qbase + wm + 15;

    const size_t base = (size_t)bh * NN * HD;
    const __half* __restrict__ Qhp = g_qh + base;
    const __half* __restrict__ Qlp = g_ql + base;
    const __half* __restrict__ Khp = g_kh + base;
    const __half* __restrict__ Klp = g_kl + base;
    const __half* __restrict__ Vhp = g_vh + base;

    uint32_t qh[4][4], ql[4][4];
    {
        const int r0 = qbase + wm + (lane >> 2);
        const int c0 = (lane & 3) * 2;
        #pragma unroll
        for (int kk = 0; kk < 4; ++kk) {
            #pragma unroll
            for (int jj = 0; jj < 4; ++jj) {
                int row = r0 + (jj & 1) * 8;
                int col = kk * 16 + c0 + (jj >> 1) * 8;
                qh[kk][jj] = *reinterpret_cast<const uint32_t*>(Qhp + (size_t)row * HD + col);
                ql[kk][jj] = *reinterpret_cast<const uint32_t*>(Qlp + (size_t)row * HD + col);
            }
        }
    }

    auto load_kv = [&](int j, int stage) {
        const int kb = j * 64;
        const uint32_t st = sb + stage * KVSTAGE_B;
        #pragma unroll
        for (int i = 0; i < 4; ++i) {
            int id = tid + i * 128;
            int r = id >> 3, c = id & 7;
            uint32_t doff = (uint32_t)(r * 144 + c * 16);
            size_t go = (size_t)(kb + r) * HD + c * 8;
            cpa16(st + 0 * KVTILE_B + doff, Khp + go);
            cpa16(st + 1 * KVTILE_B + doff, Klp + go);
            cpa16(st + 2 * KVTILE_B + doff, Vhp + go);
        }
        cpa_commit();
    };

    float o[8][4] = {};
    // running max: fp32 pair + packed fp16 mirror (quad-consistent)
    float mi0 = -1e30f, mi1 = -1e30f;
    uint32_t mip;
    {
        __half2 t = __floats2half2_rn(-1e30f, -1e30f);
        mip = *reinterpret_cast<uint32_t*>(&t);
    }
    float li0 = 0.0f, li1 = 0.0f;   // per-lane partials (quad-reduced in epilogue)

    const int ntiles = qt + 1;
    load_kv(0, 0);
    if (ntiles > 1) load_kv(1, 1);

    const int lrow = lane & 15;
    const int lcol = ((lane >> 4) & 1) * 8;
    const int vrow_base = (lane & 7) + ((lane >> 3) & 1) * 8;
    const int vcol = ((lane >> 4) & 1) * 8;

    for (int j = 0; j < ntiles; ++j) {
        if (j < ntiles - 1)
            asm volatile("cp.async.wait_group 1;" ::: "memory");
        else
            asm volatile("cp.async.wait_group 0;" ::: "memory");
        __syncthreads();

        const int j64 = 64 * j;
        const int nlim = rowmax - j64;
        const uint32_t st = sb + (j & 1) * KVSTAGE_B;

        float s[8][4] = {};

        if (j < qt) {
            // ================= dense fast path (no masks) =================
            #pragma unroll
            for (int kk = 0; kk < 4; ++kk) {
                const int kc = kk * 16 + lcol;
                #pragma unroll
                for (int npg = 0; npg < 2; ++npg) {
                    // batched loads for np pair (rows npg*32, npg*32+16)
                    uint32_t b0h[4], b0l[4], b1h[4], b1l[4];
                    uint32_t off0 = (uint32_t)((npg * 32 + lrow) * VROW + kc) * 2;
                    uint32_t off1 = (uint32_t)((npg * 32 + 16 + lrow) * VROW + kc) * 2;
                    ldmx4(b0h, st + 0 * KVTILE_B + off0);
                    ldmx4(b1h, st + 0 * KVTILE_B + off1);
                    ldmx4(b0l, st + 1 * KVTILE_B + off0);
                    ldmx4(b1l, st + 1 * KVTILE_B + off1);
                    const int f0 = npg * 4;
                    // term 1 over 4 accumulators (RAW distance 4)
                    mma16816(s[f0 + 0], qh[kk], b0h[0], b0h[2]);
                    mma16816(s[f0 + 1], qh[kk], b0h[1], b0h[3]);
                    mma16816(s[f0 + 2], qh[kk], b1h[0], b1h[2]);
                    mma16816(s[f0 + 3], qh[kk], b1h[1], b1h[3]);
                    // term 2
                    mma16816(s[f0 + 0], qh[kk], b0l[0], b0l[2]);
                    mma16816(s[f0 + 1], qh[kk], b0l[1], b0l[3]);
                    mma16816(s[f0 + 2], qh[kk], b1l[0], b1l[2]);
                    mma16816(s[f0 + 3], qh[kk], b1l[1], b1l[3]);
                    // term 3
                    mma16816(s[f0 + 0], ql[kk], b0h[0], b0h[2]);
                    mma16816(s[f0 + 1], ql[kk], b0h[1], b0h[3]);
                    mma16816(s[f0 + 2], ql[kk], b1h[0], b1h[2]);
                    mma16816(s[f0 + 3], ql[kk], b1h[1], b1h[3]);
                }
            }
        } else {
            // ================= diagonal tile (masked) =================
            #pragma unroll
            for (int kk = 0; kk < 4; ++kk) {
                const int kc = kk * 16 + lcol;
                #pragma unroll
                for (int np = 0; np < 4; ++np) {
                    if (np * 16 <= nlim) {
                        uint32_t bkh[4], bkl[4];
                        uint32_t off = (uint32_t)((np * 16 + lrow) * VROW + kc) * 2;
                        ldmx4(bkh, st + 0 * KVTILE_B + off);
                        ldmx4(bkl, st + 1 * KVTILE_B + off);
                        const int fn0 = np * 2;
                        mma16816(s[fn0 + 0], qh[kk], bkh[0], bkh[2]);
                        mma16816(s[fn0 + 1], qh[kk], bkh[1], bkh[3]);
                        mma16816(s[fn0 + 0], qh[kk], bkl[0], bkl[2]);
                        mma16816(s[fn0 + 1], qh[kk], bkl[1], bkl[3]);
                        mma16816(s[fn0 + 0], ql[kk], bkh[0], bkh[2]);
                        mma16816(s[fn0 + 1], ql[kk], bkh[1], bkh[3]);
                    }
                }
            }
            // causal mask (dense-path fn0 mapping: fn ↔ cols j64 + fn*8 — unchanged)
            const int rg0 = qbase + wm + (lane >> 2);
            #pragma unroll
            for (int fn = 0; fn < 8; ++fn) {
                const int cb = j64 + fn * 8 + (lane & 3) * 2;
                if (cb + 0 > rg0)     s[fn][0] = -1e30f;
                if (cb + 1 > rg0)     s[fn][1] = -1e30f;
                if (cb + 0 > rg0 + 8) s[fn][2] = -1e30f;
                if (cb + 1 > rg0 + 8) s[fn][3] = -1e30f;
            }
        }

        // fast-path fn remap note: dense path stores np-pair (npg) results at
        // fn = npg*4 + {0,1,2,3} where {0,1} are np0's two 8-col frags and
        // {2,3} np1's — this matches fn = np*2+f with np = npg*2(+1). Same layout.

        // ---- online softmax: packed max, per-lane li, conditional rescale ----
        {
            float m0n = mi0, m1n = mi1;
            #pragma unroll
            for (int fn = 0; fn < 8; ++fn) {
                m0n = fmaxf(m0n, fmaxf(s[fn][0], s[fn][1]));
                m1n = fmaxf(m1n, fmaxf(s[fn][2], s[fn][3]));
            }
            // quad-reduce max via packed fp16 (quad-consistent upper bound)
            __half2 mp = __floats2half2_rn(m0n, m1n);
            uint32_t mu = *reinterpret_cast<uint32_t*>(&mp);
            uint32_t t1 = __shfl_xor_sync(0xffffffffu, mu, 1);
            mp = __hmax2(mp, *reinterpret_cast<__half2*>(&t1));
            mu = *reinterpret_cast<uint32_t*>(&mp);
            uint32_t t2 = __shfl_xor_sync(0xffffffffu, mu, 2);
            mp = __hmax2(mp, *reinterpret_cast<__half2*>(&t2));
            mu = *reinterpret_cast<uint32_t*>(&mp);

            const float m0f = __low2float(mp);
            const float m1f = __high2float(mp);

            if (mu != mip) {
                const float al0 = exp2f(mi0 - m0f);
                const float al1 = exp2f(mi1 - m1f);
                li0 *= al0; li1 *= al1;
                #pragma unroll
                for (int fn = 0; fn < 8; ++fn) {
                    o[fn][0] *= al0; o[fn][1] *= al0;
                    o[fn][2] *= al1; o[fn][3] *= al1;
                }
                mi0 = m0f; mi1 = m1f; mip = mu;
            }

            float rs0 = 0.0f, rs1 = 0.0f;
            #pragma unroll
            for (int fn = 0; fn < 8; ++fn) {
                s[fn][0] = exp2f(s[fn][0] - mi0);
                s[fn][1] = exp2f(s[fn][1] - mi0);
                s[fn][2] = exp2f(s[fn][2] - mi1);
                s[fn][3] = exp2f(s[fn][3] - mi1);
                rs0 += s[fn][0] + s[fn][1];
                rs1 += s[fn][2] + s[fn][3];
            }
            li0 += rs0;   // per-lane partial; quad-reduced in epilogue
            li1 += rs1;
        }

        // ---- pack P (s dies here) ----
        uint32_t ph[4][4];
        #pragma unroll
        for (int kk = 0; kk < 4; ++kk) {
            ph[kk][0] = pack2h(s[2*kk    ][0], s[2*kk    ][1]);
            ph[kk][1] = pack2h(s[2*kk    ][2], s[2*kk    ][3]);
            ph[kk][2] = pack2h(s[2*kk + 1][0], s[2*kk + 1][1]);
            ph[kk][3] = pack2h(s[2*kk + 1][2], s[2*kk + 1][3]);
        }

        // ---- O += P V ----
        if (j < qt) {
            #pragma unroll
            for (int kk = 0; kk < 4; ++kk) {
                uint32_t v0[4], v1[4], v2[4], v3[4];
                const int vrow = kk * 16 + vrow_base;
                uint32_t offb = (uint32_t)(vrow * VROW + vcol) * 2;
                ldmx4t(v0, st + 2 * KVTILE_B + offb + 0 * 32);
                ldmx4t(v1, st + 2 * KVTILE_B + offb + 1 * 32);
                ldmx4t(v2, st + 2 * KVTILE_B + offb + 2 * 32);
                ldmx4t(v3, st + 2 * KVTILE_B + offb + 3 * 32);
                // 8 MMAs over 8 distinct accumulators
                mma16816(o[0], ph[kk], v0[0], v0[1]);
                mma16816(o[1], ph[kk], v0[2], v0[3]);
                mma16816(o[2], ph[kk], v1[0], v1[1]);
                mma16816(o[3], ph[kk], v1[2], v1[3]);
                mma16816(o[4], ph[kk], v2[0], v2[1]);
                mma16816(o[5], ph[kk], v2[2], v2[3]);
                mma16816(o[6], ph[kk], v3[0], v3[1]);
                mma16816(o[7], ph[kk], v3[2], v3[3]);
            }
        } else {
            #pragma unroll
            for (int kk = 0; kk < 4; ++kk) {
                if (kk * 16 <= nlim) {
                    #pragma unroll
                    for (int dp = 0; dp < 4; ++dp) {
                        const int vrow = kk * 16 + vrow_base;
                        uint32_t off = (uint32_t)(vrow * VROW + dp * 16 + vcol) * 2;
                        uint32_t vh_[4];
                        ldmx4t(vh_, st + 2 * KVTILE_B + off);
                        mma16816(o[dp*2 + 0], ph[kk], vh_[0], vh_[1]);
                        mma16816(o[dp*2 + 1], ph[kk], vh_[2], vh_[3]);
                    }
                }
            }
        }

        __syncthreads();
        if (j + 2 < ntiles) load_kv(j + 2, j & 1);
    }

    // ---- epilogue: quad-reduce li, divide, store ----
    li0 += __shfl_xor_sync(0xffffffffu, li0, 1);
    li0 += __shfl_xor_sync(0xffffffffu, li0, 2);
    li1 += __shfl_xor_sync(0xffffffffu, li1, 1);
    li1 += __shfl_xor_sync(0xffffffffu, li1, 2);

    const int b = bh / HH, h = bh % HH;
    const float inv0 = 1.0f / li0, inv1 = 1.0f / li1;
    const int r0 = qbase + wm + (lane >> 2);
    const int c0 = (lane & 3) * 2;
    #pragma unroll
    for (int fn = 0; fn < 8; ++fn) {
        const int col = h * HD + fn * 8 + c0;
        float* d0 = out + ((size_t)(b * NN + r0)) * DD + col;
        float* d1 = out + ((size_t)(b * NN + r0 + 8)) * DD + col;
        *reinterpret_cast<float2*>(d0) = make_float2(o[fn][0] * inv0, o[fn][1] * inv0);
        *reinterpret_cast<float2*>(d1) = make_float2(o[fn][2] * inv1, o[fn][3] * inv1);
    }
}

static const int QK_SMEM    = 2 * QK_STAGE_B;   // 81920
static const int V_SMEM     = 2 * V_STAGE_B;    // 40960
static const int FLASH_SMEM = 2 * KVSTAGE_B;    // 55296

extern "C" void kernel_launch(void* const* d_in, const int* in_sizes, int n_in,
                              void* d_out, int out_size)
{
    const float* x  = (const float*)d_in[0];
    const float* Wq = (const float*)d_in[1];
    const float* Wk = (const float*)d_in[2];
    const float* Wv = (const float*)d_in[3];
    float* out = (float*)d_out;

    static cudaStream_t s_v = nullptr;
    static cudaEvent_t e_fork = nullptr, e_join = nullptr;
    if (s_v == nullptr) {
        cudaStreamCreateWithFlags(&s_v, cudaStreamNonBlocking);
        cudaEventCreateWithFlags(&e_fork, cudaEventDisableTiming);
        cudaEventCreateWithFlags(&e_join, cudaEventDisableTiming);
        cudaFuncSetAttribute(qk_mma_kernel, cudaFuncAttributeMaxDynamicSharedMemorySize, QK_SMEM);
        cudaFuncSetAttribute(v_mma_kernel, cudaFuncAttributeMaxDynamicSharedMemorySize, V_SMEM);
        cudaFuncSetAttribute(flash_mma_kernel, cudaFuncAttributeMaxDynamicSharedMemorySize, FLASH_SMEM);
    }

    int total4 = XN / 4 + 3 * (WN / 4);
    split_kernel<<<(total4 + 255) / 256, 256>>>(
        (const float4*)x, (const float4*)Wq, (const float4*)Wk, (const float4*)Wv);

    cudaEventRecord(e_fork, 0);
    cudaStreamWaitEvent(s_v, e_fork, 0);

    qk_mma_kernel<<<dim3(DD / 128, (BB * NN) / 128, 2), 256, QK_SMEM>>>();
    v_mma_kernel<<<dim3(DD / 128, (BB * NN) / 128), 256, V_SMEM, s_v>>>();

    cudaEventRecord(e_join, s_v);
    cudaStreamWaitEvent(0, e_join, 0);

    flash_mma_kernel<<<dim3(NN / 64, BH), 128, FLASH_SMEM>>>(out);
}

// round 14
// speedup vs baseline: 1.6535x; 1.0022x over previous
#include <cuda_runtime.h>
#include <cuda_fp16.h>
#include <cstdint>
#include <math.h>

#define BB 2
#define NN 2048
#define DD 768
#define HH 12
#define HD 64
#define BH (BB*HH)
#define XN (BB*NN*DD)
#define WN (DD*DD)
#define LOG2E 1.4426950408889634f

__device__ __align__(16) __half g_xh[XN], g_xl[XN];
__device__ __align__(16) __half g_wh[3 * WN], g_wl[3 * WN];
__device__ __align__(16) __half g_qh[BH*NN*HD], g_ql[BH*NN*HD];
__device__ __align__(16) __half g_kh[BH*NN*HD], g_kl[BH*NN*HD];
__device__ __align__(16) __half g_vh[BH*NN*HD];

__device__ __forceinline__ uint32_t smem_u32(const void* p) {
    uint32_t a;
    asm("{ .reg .u64 t; cvta.to.shared.u64 t, %1; cvt.u32.u64 %0, t; }" : "=r"(a) : "l"(p));
    return a;
}
__device__ __forceinline__ uint32_t pack2h(float a, float b) {
    __half2 t = __floats2half2_rn(a, b);
    return *reinterpret_cast<uint32_t*>(&t);
}
__device__ __forceinline__ void split2h(float a, float b, uint32_t& hp, uint32_t& lp) {
    __half ha = __float2half_rn(a), hb = __float2half_rn(b);
    __half2 hh = __halves2half2(ha, hb);
    hp = *reinterpret_cast<uint32_t*>(&hh);
    lp = pack2h(a - __half2float(ha), b - __half2float(hb));
}
__device__ __forceinline__ void cpa16(uint32_t dst, const void* src) {
    asm volatile("cp.async.cg.shared.global [%0], [%1], 16;" :: "r"(dst), "l"(src) : "memory");
}
__device__ __forceinline__ void cpa_commit() {
    asm volatile("cp.async.commit_group;" ::: "memory");
}
__device__ __forceinline__ void ldmx4(uint32_t* r, uint32_t addr) {
    asm volatile("ldmatrix.sync.aligned.m8n8.x4.shared.b16 {%0,%1,%2,%3}, [%4];"
        : "=r"(r[0]), "=r"(r[1]), "=r"(r[2]), "=r"(r[3]) : "r"(addr));
}
__device__ __forceinline__ void ldmx4t(uint32_t* r, uint32_t addr) {
    asm volatile("ldmatrix.sync.aligned.m8n8.x4.trans.shared.b16 {%0,%1,%2,%3}, [%4];"
        : "=r"(r[0]), "=r"(r[1]), "=r"(r[2]), "=r"(r[3]) : "r"(addr));
}
__device__ __forceinline__ void mma16816(float* c, const uint32_t* a, uint32_t b0, uint32_t b1) {
    asm volatile("mma.sync.aligned.m16n8k16.row.col.f32.f16.f16.f32 "
        "{%0,%1,%2,%3}, {%4,%5,%6,%7}, {%8,%9}, {%0,%1,%2,%3};"
        : "+f"(c[0]), "+f"(c[1]), "+f"(c[2]), "+f"(c[3])
        : "r"(a[0]), "r"(a[1]), "r"(a[2]), "r"(a[3]), "r"(b0), "r"(b1));
}

// ---------------------------------------------------------------------------
// Split kernel. Wq pre-scaled by log2(e).
// ---------------------------------------------------------------------------
__global__ __launch_bounds__(256) void split_kernel(
    const float4* __restrict__ x, const float4* __restrict__ Wq,
    const float4* __restrict__ Wk, const float4* __restrict__ Wv)
{
    const int nx = XN / 4, nw = WN / 4;
    int i = blockIdx.x * 256 + threadIdx.x;
    if (i >= nx + 3 * nw) return;

    float4 v;
    __half *hd, *ld;
    if (i < nx) {
        v = x[i];
        hd = g_xh + (size_t)i * 4; ld = g_xl + (size_t)i * 4;
    } else {
        int j = i - nx;
        int z = j / nw, r = j - z * nw;
        const float4* w = (z == 0) ? Wq : (z == 1) ? Wk : Wv;
        v = w[r];
        if (z == 0) { v.x *= LOG2E; v.y *= LOG2E; v.z *= LOG2E; v.w *= LOG2E; }
        hd = g_wh + (size_t)z * WN + (size_t)r * 4;
        ld = g_wl + (size_t)z * WN + (size_t)r * 4;
    }
    uint32_t h0, l0, h1, l1;
    split2h(v.x, v.y, h0, l0);
    split2h(v.z, v.w, h1, l1);
    *reinterpret_cast<uint2*>(hd) = make_uint2(h0, h1);
    *reinterpret_cast<uint2*>(ld) = make_uint2(l0, l1);
}

// ---------------------------------------------------------------------------
// Q/K projection (R12/R13 best, unchanged).
// ---------------------------------------------------------------------------
#define KC 32
#define SROW 40
#define T128_B (128 * SROW * 2)
#define QK_STAGE_B (4 * T128_B)
#define NCHUNK (DD / KC)

__global__ __launch_bounds__(256, 2) void qk_mma_kernel()
{
    extern __shared__ char smc[];
    const uint32_t sb = smem_u32(smc);

    const int tid = threadIdx.x;
    const int w = tid >> 5, lane = tid & 31;
    const int wm = (w >> 1) * 32;
    const int wn = (w & 1) * 64;
    const int z = blockIdx.z;
    const int n0 = blockIdx.x * 128;
    const int m0 = blockIdx.y * 128;

    const __half* __restrict__ Bhp = g_wh + (size_t)z * WN;
    const __half* __restrict__ Blp = g_wl + (size_t)z * WN;

    auto load_chunk = [&](int kt, int stage) {
        const int kb = kt * KC;
        const uint32_t st = sb + stage * QK_STAGE_B;
        #pragma unroll
        for (int i = 0; i < 2; ++i) {
            int id = tid + i * 256;
            int r = id >> 2, c = id & 3;
            uint32_t doff = (uint32_t)(r * 80 + c * 16);
            size_t gA = (size_t)(m0 + r) * DD + kb + c * 8;
            size_t gB = (size_t)(n0 + r) * DD + kb + c * 8;
            cpa16(st + 0 * T128_B + doff, g_xh + gA);
            cpa16(st + 1 * T128_B + doff, g_xl + gA);
            cpa16(st + 2 * T128_B + doff, Bhp + gB);
            cpa16(st + 3 * T128_B + doff, Blp + gB);
        }
        cpa_commit();
    };

    float acc[2][8][4] = {};

    load_chunk(0, 0);
    load_chunk(1, 1);

    const int lrow = lane & 15;
    const int lcol = ((lane >> 4) & 1) * 8;

    for (int kt = 0; kt < NCHUNK; ++kt) {
        if (kt < NCHUNK - 1)
            asm volatile("cp.async.wait_group 1;" ::: "memory");
        else
            asm volatile("cp.async.wait_group 0;" ::: "memory");
        __syncthreads();

        const uint32_t st = sb + (kt & 1) * QK_STAGE_B;

        #pragma unroll
        for (int ks = 0; ks < 2; ++ks) {
            const int kc = ks * 16 + lcol;
            uint32_t bh[4][4], bl[4][4];
            #pragma unroll
            for (int fp = 0; fp < 4; ++fp) {
                uint32_t off = (uint32_t)((wn + fp * 16 + lrow) * SROW + kc) * 2;
                ldmx4(bh[fp], st + 2 * T128_B + off);
                ldmx4(bl[fp], st + 3 * T128_B + off);
            }
            #pragma unroll
            for (int mf = 0; mf < 2; ++mf) {
                uint32_t ah[4], al[4];
                uint32_t off = (uint32_t)((wm + mf * 16 + lrow) * SROW + kc) * 2;
                ldmx4(ah, st + 0 * T128_B + off);
                ldmx4(al, st + 1 * T128_B + off);
                #pragma unroll
                for (int fn = 0; fn < 8; ++fn) {
                    const int p = fn >> 1, f = fn & 1;
                    mma16816(acc[mf][fn], ah, bh[p][f], bh[p][f + 2]);
                }
                #pragma unroll
                for (int fn = 0; fn < 8; ++fn) {
                    const int p = fn >> 1, f = fn & 1;
                    mma16816(acc[mf][fn], ah, bl[p][f], bl[p][f + 2]);
                }
                #pragma unroll
                for (int fn = 0; fn < 8; ++fn) {
                    const int p = fn >> 1, f = fn & 1;
                    mma16816(acc[mf][fn], al, bh[p][f], bh[p][f + 2]);
                }
            }
        }
        __syncthreads();
        if (kt + 2 < NCHUNK) load_chunk(kt + 2, kt & 1);
    }

    __half* Oh = (z == 0) ? g_qh : g_kh;
    __half* Ol = (z == 0) ? g_ql : g_kl;
    const int trow = lane >> 2;
    const int tcol = (lane & 3) * 2;
    #pragma unroll
    for (int mf = 0; mf < 2; ++mf) {
        #pragma unroll
        for (int fn = 0; fn < 8; ++fn) {
            int o = n0 + wn + fn * 8 + tcol;
            int h = o >> 6, cb = o & 63;
            #pragma unroll
            for (int half = 0; half < 2; ++half) {
                int row = m0 + wm + mf * 16 + trow + half * 8;
                int b = row >> 11, n = row & (NN - 1);
                size_t idx = (((size_t)(b * HH + h)) * NN + n) * HD + cb;
                uint32_t hp, lp;
                split2h(acc[mf][fn][half * 2], acc[mf][fn][half * 2 + 1], hp, lp);
                *reinterpret_cast<uint32_t*>(Oh + idx) = hp;
                *reinterpret_cast<uint32_t*>(Ol + idx) = lp;
            }
        }
    }
}

// ---------------------------------------------------------------------------
// V projection (unchanged).
// ---------------------------------------------------------------------------
#define V_STAGE_B (2 * T128_B)

__global__ __launch_bounds__(256, 2) void v_mma_kernel()
{
    extern __shared__ char smc[];
    const uint32_t sb = smem_u32(smc);

    const int tid = threadIdx.x;
    const int w = tid >> 5, lane = tid & 31;
    const int wm = (w >> 1) * 32;
    const int wn = (w & 1) * 64;
    const int n0 = blockIdx.x * 128;
    const int m0 = blockIdx.y * 128;

    const __half* __restrict__ Bhp = g_wh + (size_t)2 * WN;

    auto load_chunk = [&](int kt, int stage) {
        const int kb = kt * KC;
        const uint32_t st = sb + stage * V_STAGE_B;
        #pragma unroll
        for (int i = 0; i < 2; ++i) {
            int id = tid + i * 256;
            int r = id >> 2, c = id & 3;
            uint32_t doff = (uint32_t)(r * 80 + c * 16);
            cpa16(st + doff, g_xh + (size_t)(m0 + r) * DD + kb + c * 8);
            cpa16(st + T128_B + doff, Bhp + (size_t)(n0 + r) * DD + kb + c * 8);
        }
        cpa_commit();
    };

    float acc[2][8][4] = {};

    load_chunk(0, 0);
    load_chunk(1, 1);

    const int lrow = lane & 15;
    const int lcol = ((lane >> 4) & 1) * 8;

    for (int kt = 0; kt < NCHUNK; ++kt) {
        if (kt < NCHUNK - 1)
            asm volatile("cp.async.wait_group 1;" ::: "memory");
        else
            asm volatile("cp.async.wait_group 0;" ::: "memory");
        __syncthreads();

        const uint32_t st = sb + (kt & 1) * V_STAGE_B;

        #pragma unroll
        for (int ks = 0; ks < 2; ++ks) {
            const int kc = ks * 16 + lcol;
            uint32_t bh[4][4];
            #pragma unroll
            for (int fp = 0; fp < 4; ++fp) {
                uint32_t off = (uint32_t)((wn + fp * 16 + lrow) * SROW + kc) * 2;
                ldmx4(bh[fp], st + T128_B + off);
            }
            #pragma unroll
            for (int mf = 0; mf < 2; ++mf) {
                uint32_t ah[4];
                uint32_t off = (uint32_t)((wm + mf * 16 + lrow) * SROW + kc) * 2;
                ldmx4(ah, st + off);
                #pragma unroll
                for (int fn = 0; fn < 8; ++fn) {
                    const int p = fn >> 1, f = fn & 1;
                    mma16816(acc[mf][fn], ah, bh[p][f], bh[p][f + 2]);
                }
            }
        }
        __syncthreads();
        if (kt + 2 < NCHUNK) load_chunk(kt + 2, kt & 1);
    }

    const int trow = lane >> 2;
    const int tcol = (lane & 3) * 2;
    #pragma unroll
    for (int mf = 0; mf < 2; ++mf) {
        #pragma unroll
        for (int fn = 0; fn < 8; ++fn) {
            int o = n0 + wn + fn * 8 + tcol;
            int h = o >> 6, cb = o & 63;
            #pragma unroll
            for (int half = 0; half < 2; ++half) {
                int row = m0 + wm + mf * 16 + trow + half * 8;
                int b = row >> 11, n = row & (NN - 1);
                size_t idx = (((size_t)(b * HH + h)) * NN + n) * HD + cb;
                *reinterpret_cast<uint32_t*>(g_vh + idx) =
                    pack2h(acc[mf][fn][half * 2], acc[mf][fn][half * 2 + 1]);
            }
        }
    }
}

// ---------------------------------------------------------------------------
// Flash attention: BLOCK_M=64, 4 warps x 16 rows, BLOCK_N=64, 3 CTAs/SM.
// Q hi/lo in SMEM (frees regs); S loop: 10 ldsm up front, 24 MMAs term-major
// over 8 accumulators (RAW distance 8). PV distance 8. exp2 domain.
// ---------------------------------------------------------------------------
#define VROW 72
#define QT_B (64 * VROW * 2)        // 9216 (one 64x64 fp16 tile, padded rows)
#define KVTILE_B (64 * VROW * 2)    // 9216
#define KVSTAGE_B (3 * KVTILE_B)    // 27648

__global__ __launch_bounds__(128, 3) void flash_mma_kernel(float* __restrict__ out)
{
    extern __shared__ char smc[];
    const uint32_t sb = smem_u32(smc);
    const uint32_t sQh = sb;
    const uint32_t sQl = sb + QT_B;
    const uint32_t sKV = sb + 2 * QT_B;

    const int tid = threadIdx.x, wid = tid >> 5, lane = tid & 31;
    const int bh = blockIdx.y;
    const int qt = (int)gridDim.x - 1 - (int)blockIdx.x;   // heavy tiles first
    const int qbase = qt * 64;
    const int wm = wid * 16;
    const int rowmax = qbase + wm + 15;

    const size_t base = (size_t)bh * NN * HD;
    const __half* __restrict__ Qhp = g_qh + base;
    const __half* __restrict__ Qlp = g_ql + base;
    const __half* __restrict__ Khp = g_kh + base;
    const __half* __restrict__ Klp = g_kl + base;
    const __half* __restrict__ Vhp = g_vh + base;

    auto load_kv = [&](int j, int stage) {
        const int kb = j * 64;
        const uint32_t st = sKV + stage * KVSTAGE_B;
        #pragma unroll
        for (int i = 0; i < 4; ++i) {
            int id = tid + i * 128;
            int r = id >> 3, c = id & 7;
            uint32_t doff = (uint32_t)(r * 144 + c * 16);
            size_t go = (size_t)(kb + r) * HD + c * 8;
            cpa16(st + 0 * KVTILE_B + doff, Khp + go);
            cpa16(st + 1 * KVTILE_B + doff, Klp + go);
            cpa16(st + 2 * KVTILE_B + doff, Vhp + go);
        }
        cpa_commit();
    };

    // Q tile (hi+lo) into smem; joins the first commit group (with KV0)
    #pragma unroll
    for (int i = 0; i < 4; ++i) {
        int id = tid + i * 128;
        int r = id >> 3, c = id & 7;
        uint32_t doff = (uint32_t)(r * 144 + c * 16);
        size_t go = (size_t)(qbase + r) * HD + c * 8;
        cpa16(sQh + doff, Qhp + go);
        cpa16(sQl + doff, Qlp + go);
    }

    float o[8][4] = {};
    float mi0 = -1e30f, mi1 = -1e30f;
    uint32_t mip;
    {
        __half2 t = __floats2half2_rn(-1e30f, -1e30f);
        mip = *reinterpret_cast<uint32_t*>(&t);
    }
    float li0 = 0.0f, li1 = 0.0f;

    const int ntiles = qt + 1;
    load_kv(0, 0);              // commit group 0 (Q + KV0)
    if (ntiles > 1) load_kv(1, 1);

    const int lrow = lane & 15;
    const int lcol = ((lane >> 4) & 1) * 8;
    const int vrow_base = (lane & 7) + ((lane >> 3) & 1) * 8;
    const int vcol = ((lane >> 4) & 1) * 8;

    for (int j = 0; j < ntiles; ++j) {
        if (j < ntiles - 1)
            asm volatile("cp.async.wait_group 1;" ::: "memory");
        else
            asm volatile("cp.async.wait_group 0;" ::: "memory");
        __syncthreads();

        const int j64 = 64 * j;
        const int nlim = rowmax - j64;
        const uint32_t st = sKV + (j & 1) * KVSTAGE_B;

        float s[8][4] = {};

        if (j < qt) {
            // ============ dense fast path: distance-8 MMA ordering ============
            #pragma unroll
            for (int kk = 0; kk < 4; ++kk) {
                const int kc = kk * 16 + lcol;
                uint32_t qoff = (uint32_t)((wm + lrow) * VROW + kc) * 2;
                uint32_t qhf[4], qlf[4];
                ldmx4(qhf, sQh + qoff);
                ldmx4(qlf, sQl + qoff);
                uint32_t bh_[4][4], bl_[4][4];
                #pragma unroll
                for (int np = 0; np < 4; ++np) {
                    uint32_t off = (uint32_t)((np * 16 + lrow) * VROW + kc) * 2;
                    ldmx4(bh_[np], st + 0 * KVTILE_B + off);
                    ldmx4(bl_[np], st + 1 * KVTILE_B + off);
                }
                // term 1: 8 MMAs over 8 accumulators
                #pragma unroll
                for (int np = 0; np < 4; ++np) {
                    mma16816(s[np*2 + 0], qhf, bh_[np][0], bh_[np][2]);
                    mma16816(s[np*2 + 1], qhf, bh_[np][1], bh_[np][3]);
                }
                // term 2
                #pragma unroll
                for (int np = 0; np < 4; ++np) {
                    mma16816(s[np*2 + 0], qhf, bl_[np][0], bl_[np][2]);
                    mma16816(s[np*2 + 1], qhf, bl_[np][1], bl_[np][3]);
                }
                // term 3
                #pragma unroll
                for (int np = 0; np < 4; ++np) {
                    mma16816(s[np*2 + 0], qlf, bh_[np][0], bh_[np][2]);
                    mma16816(s[np*2 + 1], qlf, bh_[np][1], bh_[np][3]);
                }
            }
        } else {
            // ============ diagonal tile (masked) ============
            #pragma unroll
            for (int kk = 0; kk < 4; ++kk) {
                const int kc = kk * 16 + lcol;
                uint32_t qoff = (uint32_t)((wm + lrow) * VROW + kc) * 2;
                uint32_t qhf[4], qlf[4];
                ldmx4(qhf, sQh + qoff);
                ldmx4(qlf, sQl + qoff);
                #pragma unroll
                for (int np = 0; np < 4; ++np) {
                    if (np * 16 <= nlim) {
                        uint32_t bkh[4], bkl[4];
                        uint32_t off = (uint32_t)((np * 16 + lrow) * VROW + kc) * 2;
                        ldmx4(bkh, st + 0 * KVTILE_B + off);
                        ldmx4(bkl, st + 1 * KVTILE_B + off);
                        const int fn0 = np * 2;
                        mma16816(s[fn0 + 0], qhf, bkh[0], bkh[2]);
                        mma16816(s[fn0 + 1], qhf, bkh[1], bkh[3]);
                        mma16816(s[fn0 + 0], qhf, bkl[0], bkl[2]);
                        mma16816(s[fn0 + 1], qhf, bkl[1], bkl[3]);
                        mma16816(s[fn0 + 0], qlf, bkh[0], bkh[2]);
                        mma16816(s[fn0 + 1], qlf, bkh[1], bkh[3]);
                    }
                }
            }
            const int rg0 = qbase + wm + (lane >> 2);
            #pragma unroll
            for (int fn = 0; fn < 8; ++fn) {
                const int cb = j64 + fn * 8 + (lane & 3) * 2;
                if (cb + 0 > rg0)     s[fn][0] = -1e30f;
                if (cb + 1 > rg0)     s[fn][1] = -1e30f;
                if (cb + 0 > rg0 + 8) s[fn][2] = -1e30f;
                if (cb + 1 > rg0 + 8) s[fn][3] = -1e30f;
            }
        }

        // ---- online softmax: packed max, per-lane li, conditional rescale ----
        {
            float m0n = mi0, m1n = mi1;
            #pragma unroll
            for (int fn = 0; fn < 8; ++fn) {
                m0n = fmaxf(m0n, fmaxf(s[fn][0], s[fn][1]));
                m1n = fmaxf(m1n, fmaxf(s[fn][2], s[fn][3]));
            }
            __half2 mp = __floats2half2_rn(m0n, m1n);
            uint32_t mu = *reinterpret_cast<uint32_t*>(&mp);
            uint32_t t1 = __shfl_xor_sync(0xffffffffu, mu, 1);
            mp = __hmax2(mp, *reinterpret_cast<__half2*>(&t1));
            mu = *reinterpret_cast<uint32_t*>(&mp);
            uint32_t t2 = __shfl_xor_sync(0xffffffffu, mu, 2);
            mp = __hmax2(mp, *reinterpret_cast<__half2*>(&t2));
            mu = *reinterpret_cast<uint32_t*>(&mp);

            const float m0f = __low2float(mp);
            const float m1f = __high2float(mp);

            if (mu != mip) {
                const float al0 = exp2f(mi0 - m0f);
                const float al1 = exp2f(mi1 - m1f);
                li0 *= al0; li1 *= al1;
                #pragma unroll
                for (int fn = 0; fn < 8; ++fn) {
                    o[fn][0] *= al0; o[fn][1] *= al0;
                    o[fn][2] *= al1; o[fn][3] *= al1;
                }
                mi0 = m0f; mi1 = m1f; mip = mu;
            }

            float rs0 = 0.0f, rs1 = 0.0f;
            #pragma unroll
            for (int fn = 0; fn < 8; ++fn) {
                s[fn][0] = exp2f(s[fn][0] - mi0);
                s[fn][1] = exp2f(s[fn][1] - mi0);
                s[fn][2] = exp2f(s[fn][2] - mi1);
                s[fn][3] = exp2f(s[fn][3] - mi1);
                rs0 += s[fn][0] + s[fn][1];
                rs1 += s[fn][2] + s[fn][3];
            }
            li0 += rs0;
            li1 += rs1;
        }

        // ---- pack P ----
        uint32_t ph[4][4];
        #pragma unroll
        for (int kk = 0; kk < 4; ++kk) {
            ph[kk][0] = pack2h(s[2*kk    ][0], s[2*kk    ][1]);
            ph[kk][1] = pack2h(s[2*kk    ][2], s[2*kk    ][3]);
            ph[kk][2] = pack2h(s[2*kk + 1][0], s[2*kk + 1][1]);
            ph[kk][3] = pack2h(s[2*kk + 1][2], s[2*kk + 1][3]);
        }

        // ---- O += P V ----
        if (j < qt) {
            #pragma unroll
            for (int kk = 0; kk < 4; ++kk) {
                uint32_t v0[4], v1[4], v2[4], v3[4];
                const int vrow = kk * 16 + vrow_base;
                uint32_t offb = (uint32_t)(vrow * VROW + vcol) * 2;
                ldmx4t(v0, st + 2 * KVTILE_B + offb + 0 * 32);
                ldmx4t(v1, st + 2 * KVTILE_B + offb + 1 * 32);
                ldmx4t(v2, st + 2 * KVTILE_B + offb + 2 * 32);
                ldmx4t(v3, st + 2 * KVTILE_B + offb + 3 * 32);
                mma16816(o[0], ph[kk], v0[0], v0[1]);
                mma16816(o[1], ph[kk], v0[2], v0[3]);
                mma16816(o[2], ph[kk], v1[0], v1[1]);
                mma16816(o[3], ph[kk], v1[2], v1[3]);
                mma16816(o[4], ph[kk], v2[0], v2[1]);
                mma16816(o[5], ph[kk], v2[2], v2[3]);
                mma16816(o[6], ph[kk], v3[0], v3[1]);
                mma16816(o[7], ph[kk], v3[2], v3[3]);
            }
        } else {
            #pragma unroll
            for (int kk = 0; kk < 4; ++kk) {
                if (kk * 16 <= nlim) {
                    #pragma unroll
                    for (int dp = 0; dp < 4; ++dp) {
                        const int vrow = kk * 16 + vrow_base;
                        uint32_t off = (uint32_t)(vrow * VROW + dp * 16 + vcol) * 2;
                        uint32_t vh_[4];
                        ldmx4t(vh_, st + 2 * KVTILE_B + off);
                        mma16816(o[dp*2 + 0], ph[kk], vh_[0], vh_[1]);
                        mma16816(o[dp*2 + 1], ph[kk], vh_[2], vh_[3]);
                    }
                }
            }
        }

        __syncthreads();
        if (j + 2 < ntiles) load_kv(j + 2, j & 1);
    }

    // ---- epilogue: quad-reduce li, divide, store ----
    li0 += __shfl_xor_sync(0xffffffffu, li0, 1);
    li0 += __shfl_xor_sync(0xffffffffu, li0, 2);
    li1 += __shfl_xor_sync(0xffffffffu, li1, 1);
    li1 += __shfl_xor_sync(0xffffffffu, li1, 2);

    const int b = bh / HH, h = bh % HH;
    const float inv0 = 1.0f / li0, inv1 = 1.0f / li1;
    const int r0 = qbase + wm + (lane >> 2);
    const int c0 = (lane & 3) * 2;
    #pragma unroll
    for (int fn = 0; fn < 8; ++fn) {
        const int col = h * HD + fn * 8 + c0;
        float* d0 = out + ((size_t)(b * NN + r0)) * DD + col;
        float* d1 = out + ((size_t)(b * NN + r0 + 8)) * DD + col;
        *reinterpret_cast<float2*>(d0) = make_float2(o[fn][0] * inv0, o[fn][1] * inv0);
        *reinterpret_cast<float2*>(d1) = make_float2(o[fn][2] * inv1, o[fn][3] * inv1);
    }
}

static const int QK_SMEM    = 2 * QK_STAGE_B;             // 81920
static const int V_SMEM     = 2 * V_STAGE_B;              // 40960
static const int FLASH_SMEM = 2 * QT_B + 2 * KVSTAGE_B;   // 73728

extern "C" void kernel_launch(void* const* d_in, const int* in_sizes, int n_in,
                              void* d_out, int out_size)
{
    const float* x  = (const float*)d_in[0];
    const float* Wq = (const float*)d_in[1];
    const float* Wk = (const float*)d_in[2];
    const float* Wv = (const float*)d_in[3];
    float* out = (float*)d_out;

    static cudaStream_t s_v = nullptr;
    static cudaEvent_t e_fork = nullptr, e_join = nullptr;
    if (s_v == nullptr) {
        cudaStreamCreateWithFlags(&s_v, cudaStreamNonBlocking);
        cudaEventCreateWithFlags(&e_fork, cudaEventDisableTiming);
        cudaEventCreateWithFlags(&e_join, cudaEventDisableTiming);
        cudaFuncSetAttribute(qk_mma_kernel, cudaFuncAttributeMaxDynamicSharedMemorySize, QK_SMEM);
        cudaFuncSetAttribute(v_mma_kernel, cudaFuncAttributeMaxDynamicSharedMemorySize, V_SMEM);
        cudaFuncSetAttribute(flash_mma_kernel, cudaFuncAttributeMaxDynamicSharedMemorySize, FLASH_SMEM);
    }

    int total4 = XN / 4 + 3 * (WN / 4);
    split_kernel<<<(total4 + 255) / 256, 256>>>(
        (const float4*)x, (const float4*)Wq, (const float4*)Wk, (const float4*)Wv);

    cudaEventRecord(e_fork, 0);
    cudaStreamWaitEvent(s_v, e_fork, 0);

    qk_mma_kernel<<<dim3(DD / 128, (BB * NN) / 128, 2), 256, QK_SMEM>>>();
    v_mma_kernel<<<dim3(DD / 128, (BB * NN) / 128), 256, V_SMEM, s_v>>>();

    cudaEventRecord(e_join, s_v);
    cudaStreamWaitEvent(0, e_join, 0);

    flash_mma_kernel<<<dim3(NN / 64, BH), 128, FLASH_SMEM>>>(out);
}